// round 11
// baseline (speedup 1.0000x reference)
#include <cuda_runtime.h>
#include <cuda_bf16.h>
#include <math.h>
#include <stdint.h>

#define BB    4
#define TT    128
#define FRR   64
#define LL    8192
#define DIMM  384
#define NHEAD 12
#define HDIM  32
#define NTOK  (BB*LL)
#define QKVN  (3*DIMM)
#define FFN   (4*DIMM)

typedef __nv_bfloat16  bf16;
typedef __nv_bfloat162 bf162;

// ---------------------------------------------------------------------------
// Scratch
// ---------------------------------------------------------------------------
__device__ float g_xs  [(size_t)NTOK * DIMM];
__device__ bf16  g_xnb [(size_t)NTOK * DIMM];
__device__ float g_qkv [(size_t)NTOK * QKVN];
__device__ float g_ysum[(size_t)NTOK * DIMM];
__device__ bf16  g_ysb [(size_t)NTOK * DIMM];
__device__ bf16  g_hb  [(size_t)NTOK * DIMM];
__device__ bf16  g_h1b [(size_t)NTOK * FFN];
__device__ bf16  g_wqkv [QKVN * DIMM];
__device__ bf16  g_wproj[DIMM * DIMM];
__device__ bf16  g_w1   [FFN * DIMM];
__device__ bf16  g_w2   [DIMM * FFN];

// ---------------------------------------------------------------------------
// Weight prep: w [K][N] f32 -> wt [N][K] bf16
// ---------------------------------------------------------------------------
__global__ void wprep_kernel(const float* __restrict__ w,
                             bf16* __restrict__ wt, int K, int N) {
    __shared__ float tile[32][33];
    int n0 = blockIdx.x * 32, k0 = blockIdx.y * 32;
    int tx = threadIdx.x, ty = threadIdx.y;
    #pragma unroll
    for (int i = 0; i < 32; i += 8)
        tile[ty + i][tx] = w[(size_t)(k0 + ty + i) * N + n0 + tx];
    __syncthreads();
    #pragma unroll
    for (int i = 0; i < 32; i += 8)
        wt[(size_t)(n0 + ty + i) * K + k0 + tx] =
            __float2bfloat16_rn(tile[tx][ty + i]);
}

// ---------------------------------------------------------------------------
// Fused input transpose + rms1
// ---------------------------------------------------------------------------
__global__ __launch_bounds__(256)
void fuse_in_kernel(const float* __restrict__ x,
                    const float* __restrict__ n1,
                    float* __restrict__ xs, bf16* __restrict__ xnb) {
    __shared__ float tile[DIMM][17];
    __shared__ float rinv[16];
    int tid = threadIdx.x;
    int l0 = blockIdx.x * 16;
    int b  = blockIdx.y;
    const float* xb = x + (size_t)b * DIMM * LL + l0;

    #pragma unroll
    for (int it = 0; it < 24; it++) {
        int idx = tid + it * 256;
        int d = idx >> 4, c = idx & 15;
        tile[d][c] = xb[(size_t)d * LL + c];
    }
    __syncthreads();

    int tok = tid >> 4, j = tid & 15;
    float s = 0.f;
    #pragma unroll
    for (int k = 0; k < 24; k++) {
        float v = tile[j + 16 * k][tok];
        s += v * v;
    }
    #pragma unroll
    for (int m = 8; m >= 1; m >>= 1)
        s += __shfl_xor_sync(0xffffffffu, s, m);
    if (j == 0) rinv[tok] = rsqrtf(s * (1.0f / DIMM) + 1e-6f);
    __syncthreads();

    size_t gbase = ((size_t)b * LL + l0) * DIMM;
    #pragma unroll
    for (int it = 0; it < 24; it++) {
        int idx = tid + it * 256;
        int t2 = idx / DIMM, d = idx - t2 * DIMM;
        float raw = tile[d][t2];
        xs[gbase + (size_t)t2 * DIMM + d] = raw;
        xnb[gbase + (size_t)t2 * DIMM + d] =
            __float2bfloat16_rn(raw * rinv[t2] * n1[d]);
    }
}

// ---------------------------------------------------------------------------
// Output transpose
// ---------------------------------------------------------------------------
__global__ void transpose_kernel(const float* __restrict__ in,
                                 float* __restrict__ out,
                                 int rows, int cols) {
    __shared__ float tile[32][33];
    int bx = blockIdx.x * 32;
    int by = blockIdx.y * 32;
    size_t plane = (size_t)rows * cols;
    const float* inb = in + (size_t)blockIdx.z * plane;
    float* outb      = out + (size_t)blockIdx.z * plane;
    int tx = threadIdx.x, ty = threadIdx.y;
    #pragma unroll
    for (int i = 0; i < 32; i += 8)
        tile[ty + i][tx] = inb[(size_t)(by + ty + i) * cols + bx + tx];
    __syncthreads();
    #pragma unroll
    for (int i = 0; i < 32; i += 8)
        outb[(size_t)(bx + ty + i) * rows + by + tx] = tile[tx][ty + i];
}

// ---------------------------------------------------------------------------
// rms2
// ---------------------------------------------------------------------------
__global__ void rms_kernel(const float* __restrict__ in,
                           const float* __restrict__ scale,
                           bf16* __restrict__ out) {
    int tok = blockIdx.x;
    int tid = threadIdx.x;
    const float* row = in + (size_t)tok * DIMM;
    float v0 = row[tid], v1 = row[tid + 128], v2 = row[tid + 256];
    float s = v0*v0 + v1*v1 + v2*v2;
    #pragma unroll
    for (int off = 16; off > 0; off >>= 1)
        s += __shfl_down_sync(0xffffffffu, s, off);
    __shared__ float red[4];
    if ((tid & 31) == 0) red[tid >> 5] = s;
    __syncthreads();
    if (tid == 0) {
        float t = red[0] + red[1] + red[2] + red[3];
        red[0] = rsqrtf(t * (1.0f / DIMM) + 1e-6f);
    }
    __syncthreads();
    float rinv = red[0];
    bf16* orow = out + (size_t)tok * DIMM;
    orow[tid]       = __float2bfloat16_rn(v0 * rinv * scale[tid]);
    orow[tid + 128] = __float2bfloat16_rn(v1 * rinv * scale[tid + 128]);
    orow[tid + 256] = __float2bfloat16_rn(v2 * rinv * scale[tid + 256]);
}

// ---------------------------------------------------------------------------
// QK rms-norm + RoPE
// ---------------------------------------------------------------------------
__global__ __launch_bounds__(128)
void qkrope_kernel(float* __restrict__ qkv,
                   const float* __restrict__ nq,
                   const float* __restrict__ nk,
                   const float* __restrict__ cosT,
                   const float* __restrict__ sinT) {
    int tid = threadIdx.x;
    int lane = tid & 31;
    int tok = blockIdx.x * 4 + (tid >> 5);
    size_t base = (size_t)tok * QKVN;
    float* qp = qkv + base;
    float* kp = qkv + base + DIMM;

    float4 qv[3], kv[3];
    float ssq = 0.f, ssk = 0.f;
    #pragma unroll
    for (int i = 0; i < 3; i++) {
        int e0 = i * 128 + lane * 4;
        qv[i] = *(const float4*)(qp + e0);
        kv[i] = *(const float4*)(kp + e0);
        ssq += qv[i].x*qv[i].x + qv[i].y*qv[i].y + qv[i].z*qv[i].z + qv[i].w*qv[i].w;
        ssk += kv[i].x*kv[i].x + kv[i].y*kv[i].y + kv[i].z*kv[i].z + kv[i].w*kv[i].w;
    }
    #pragma unroll
    for (int m = 16; m >= 1; m >>= 1) {
        ssq += __shfl_xor_sync(0xffffffffu, ssq, m);
        ssk += __shfl_xor_sync(0xffffffffu, ssk, m);
    }
    float rq = rsqrtf(ssq * (1.0f / DIMM) + 1e-6f);
    float rk = rsqrtf(ssk * (1.0f / DIMM) + 1e-6f);

    int l = tok & (LL - 1);
    int j2 = 2 * (lane & 7);
    float c0 = cosT[l * 16 + j2],     s0 = sinT[l * 16 + j2];
    float c1 = cosT[l * 16 + j2 + 1], s1 = sinT[l * 16 + j2 + 1];

    #pragma unroll
    for (int i = 0; i < 3; i++) {
        int e0 = i * 128 + lane * 4;
        float4 nqv = *(const float4*)(nq + e0);
        float4 nkv = *(const float4*)(nk + e0);
        float a0 = qv[i].x * rq * nqv.x, a1 = qv[i].y * rq * nqv.y;
        float a2 = qv[i].z * rq * nqv.z, a3 = qv[i].w * rq * nqv.w;
        float4 o;
        o.x = a0 * c0 - a1 * s0;  o.y = a0 * s0 + a1 * c0;
        o.z = a2 * c1 - a3 * s1;  o.w = a2 * s1 + a3 * c1;
        *(float4*)(qp + e0) = o;
        float b0 = kv[i].x * rk * nkv.x, b1 = kv[i].y * rk * nkv.y;
        float b2 = kv[i].z * rk * nkv.z, b3 = kv[i].w * rk * nkv.w;
        float4 p;
        p.x = b0 * c0 - b1 * s0;  p.y = b0 * s0 + b1 * c0;
        p.z = b2 * c1 - b3 * s1;  p.w = b2 * s1 + b3 * c1;
        *(float4*)(kp + e0) = p;
    }
}

// ---------------------------------------------------------------------------
// Attention (single-pass softmax)
// ---------------------------------------------------------------------------
template <int VAR>
__device__ __forceinline__ int tok_of(int g, int s) {
    if (VAR == 0) { int b = g >> 7, t = g & 127; return b * LL + t * FRR + s; }
    if (VAR == 1) { int b = g >> 6, fr = g & 63; return b * LL + s * FRR + fr; }
    int b = g >> 8, r = g & 255;
    int t1 = r >> 3, f1 = r & 7;
    int t2 = s >> 3, f2 = s & 7;
    return b * LL + (t1 * 4 + t2) * FRR + f1 * 8 + f2;
}

template <int VAR, int S, int MODE>
__global__ void attn_kernel(const float* __restrict__ qkv,
                            float* __restrict__ ysum,
                            bf16* __restrict__ ysb) {
    __shared__ float Ks[S][HDIM];
    __shared__ float Vs[S][HDIM];
    int g = blockIdx.x, h = blockIdx.y, tid = threadIdx.x;

    for (int idx = tid; idx < S * HDIM; idx += S) {
        int r = idx >> 5, d = idx & 31;
        size_t base = (size_t)tok_of<VAR>(g, r) * QKVN + h * HDIM;
        Ks[r][d] = qkv[base + 384 + d];
        Vs[r][d] = qkv[base + 768 + d];
    }
    size_t qbase = (size_t)tok_of<VAR>(g, tid) * QKVN + h * HDIM;
    float q[HDIM];
    #pragma unroll
    for (int d4 = 0; d4 < 8; d4++) {
        float4 v = *(const float4*)(qkv + qbase + d4 * 4);
        q[d4*4+0] = v.x; q[d4*4+1] = v.y; q[d4*4+2] = v.z; q[d4*4+3] = v.w;
    }
    __syncthreads();

    const float rscale = 0.17677669529663687f;
    float lsum = 0.f;
    float acc[HDIM];
    #pragma unroll
    for (int d = 0; d < HDIM; d++) acc[d] = 0.f;

    for (int j = 0; j < S; j++) {
        float s = 0.f;
        #pragma unroll
        for (int d = 0; d < HDIM; d++) s += q[d] * Ks[j][d];
        float p = __expf(s * rscale);
        lsum += p;
        #pragma unroll
        for (int d = 0; d < HDIM; d++) acc[d] += p * Vs[j][d];
    }
    float inv = 1.f / lsum;
    size_t obase = (size_t)tok_of<VAR>(g, tid) * DIMM + h * HDIM;
    #pragma unroll
    for (int d = 0; d < HDIM; d++) {
        if (MODE == 0)      ysum[obase + d] = acc[d] * inv;
        else if (MODE == 1) ysum[obase + d] += acc[d] * inv;
        else {
            float t = ysum[obase + d] + acc[d] * inv;
            ysum[obase + d] = t;
            ysb[obase + d] = __float2bfloat16_rn(t);
        }
    }
}

// ---------------------------------------------------------------------------
// bf16 mma.sync GEMM, ldmatrix fragments, 3-stage cp.async pipeline +
// double-buffered register fragments.
// C(M,N) = epi(A(M,K) @ Wt(N,K)^T + bias)
// 128x128x64 tile, 256 threads (8 warps 4m x 2n), warp tile 32x64.
// smem: 3 stages x ([128][72] A + [128][72] B) bf16 = 110.6 KB dynamic.
// EPI 0: f32 store; EPI 1: bf16 gelu store; EPI 2: f32 +=.
// ---------------------------------------------------------------------------
#define GBM 128
#define GBN 128
#define GBK 64
#define KSTR 72
#define STAGE_BYTES (GBM * KSTR * 2)                 // 18432 per matrix stage
#define GEMM_SMEM_BYTES (6 * STAGE_BYTES)            // 3 stages x (A+B)

__device__ __forceinline__ float gelu_tanh(float x) {
    float c = 0.7978845608028654f;
    float t = tanhf(c * (x + 0.044715f * x * x * x));
    return 0.5f * x * (1.0f + t);
}

__device__ __forceinline__ void cp16(uint32_t smem, const void* gmem) {
    asm volatile("cp.async.cg.shared.global [%0], [%1], 16;\n" :: "r"(smem), "l"(gmem));
}
#define CP_COMMIT() asm volatile("cp.async.commit_group;\n" ::: "memory")
#define CP_WAIT(n)  asm volatile("cp.async.wait_group %0;\n" :: "n"(n) : "memory")

__device__ __forceinline__ void ldsm4(unsigned& r0, unsigned& r1,
                                      unsigned& r2, unsigned& r3, unsigned addr) {
    asm volatile("ldmatrix.sync.aligned.m8n8.x4.shared.b16 {%0,%1,%2,%3}, [%4];\n"
                 : "=r"(r0), "=r"(r1), "=r"(r2), "=r"(r3) : "r"(addr));
}

__device__ __forceinline__ void mma_bf16(float* c, const unsigned* a, const unsigned* b) {
    asm volatile(
        "mma.sync.aligned.m16n8k16.row.col.f32.bf16.bf16.f32 "
        "{%0,%1,%2,%3}, {%4,%5,%6,%7}, {%8,%9}, {%0,%1,%2,%3};\n"
        : "+f"(c[0]), "+f"(c[1]), "+f"(c[2]), "+f"(c[3])
        : "r"(a[0]), "r"(a[1]), "r"(a[2]), "r"(a[3]), "r"(b[0]), "r"(b[1]));
}

template <int EPI>
__global__ __launch_bounds__(256)
void mma_gemm(const bf16* __restrict__ A, const bf16* __restrict__ Wt,
              const float* __restrict__ bias, void* __restrict__ Cv,
              int M, int N, int K) {
    extern __shared__ char dynsmem[];
    // stages: A0 A1 A2 B0 B1 B2, each STAGE_BYTES
    uint32_t As_u = (uint32_t)__cvta_generic_to_shared(dynsmem);
    uint32_t Bs_u = As_u + 3 * STAGE_BYTES;

    int tid  = threadIdx.x;
    int n0   = blockIdx.x * GBN, m0 = blockIdx.y * GBM;
    int warp = tid >> 5, lane = tid & 31;
    int wm   = (warp & 3) * 32;
    int wn   = (warp >> 2) * 64;

    const bf16* Abase = A  + (size_t)m0 * K;
    const bf16* Bbase = Wt + (size_t)n0 * K;

    // ldmatrix per-lane address pieces (verified mapping)
    int mrow = lane & 7;
    int sel  = lane >> 3;
    int a_row_add = (sel & 1) * 8 + mrow;
    int a_k_add   = (sel >> 1) * 8;
    int b_row_add = (sel >> 1) * 8 + mrow;
    int b_k_add   = (sel & 1) * 8;

    float c[2][8][4];
    #pragma unroll
    for (int mt = 0; mt < 2; mt++)
        #pragma unroll
        for (int nt = 0; nt < 8; nt++)
            #pragma unroll
            for (int r = 0; r < 4; r++) c[mt][nt][r] = 0.f;

    auto load_tiles = [&](int buf, int k0) {
        uint32_t Ad = As_u + buf * STAGE_BYTES;
        uint32_t Bd = Bs_u + buf * STAGE_BYTES;
        #pragma unroll
        for (int i = 0; i < 4; i++) {
            int ch = tid + i * 256;
            int r = ch >> 3, cc = ch & 7;
            uint32_t so = (uint32_t)(r * KSTR + cc * 8) * 2;
            cp16(Ad + so, Abase + (size_t)r * K + k0 + cc * 8);
            cp16(Bd + so, Bbase + (size_t)r * K + k0 + cc * 8);
        }
    };

    int kTiles = K / GBK;          // 6 or 24 — always >= 2
    load_tiles(0, 0);
    CP_COMMIT();
    load_tiles(1, GBK);
    CP_COMMIT();

    unsigned af[2][2][4], bf[2][8][2];   // [regset][...]

    for (int kt = 0; kt < kTiles; kt++) {
        int buf = kt % 3;
        if (kt + 2 < kTiles) {
            load_tiles((kt + 2) % 3, (kt + 2) * GBK);
            CP_COMMIT();
            CP_WAIT(2);
        } else if (kt + 1 < kTiles) {
            CP_WAIT(1);
        } else {
            CP_WAIT(0);
        }
        __syncthreads();

        uint32_t Abuf = As_u + buf * STAGE_BYTES;
        uint32_t Bbuf = Bs_u + buf * STAGE_BYTES;

        auto ld_frags = [&](int set, int ks) {
            #pragma unroll
            for (int mt = 0; mt < 2; mt++) {
                uint32_t addr = Abuf +
                    (uint32_t)((wm + mt * 16 + a_row_add) * KSTR + ks + a_k_add) * 2;
                ldsm4(af[set][mt][0], af[set][mt][1], af[set][mt][2], af[set][mt][3], addr);
            }
            #pragma unroll
            for (int np = 0; np < 4; np++) {
                uint32_t addr = Bbuf +
                    (uint32_t)((wn + np * 16 + b_row_add) * KSTR + ks + b_k_add) * 2;
                ldsm4(bf[set][2*np][0], bf[set][2*np][1],
                      bf[set][2*np+1][0], bf[set][2*np+1][1], addr);
            }
        };

        ld_frags(0, 0);
        #pragma unroll
        for (int s = 0; s < GBK / 16; s++) {
            int cur = s & 1;
            if (s < GBK / 16 - 1) ld_frags(cur ^ 1, (s + 1) * 16);
            #pragma unroll
            for (int mt = 0; mt < 2; mt++)
                #pragma unroll
                for (int nt = 0; nt < 8; nt++)
                    mma_bf16(c[mt][nt], af[cur][mt], bf[cur][nt]);
        }
        __syncthreads();
    }

    int gid  = lane >> 2, tid4 = lane & 3;
    #pragma unroll
    for (int mt = 0; mt < 2; mt++) {
        int r0 = m0 + wm + mt * 16 + gid;
        int r1 = r0 + 8;
        #pragma unroll
        for (int nt = 0; nt < 8; nt++) {
            int cc = n0 + wn + nt * 8 + 2 * tid4;
            float b0 = bias[cc], b1 = bias[cc + 1];
            float v00 = c[mt][nt][0] + b0, v01 = c[mt][nt][1] + b1;
            float v10 = c[mt][nt][2] + b0, v11 = c[mt][nt][3] + b1;
            if (EPI == 0) {
                float* C = (float*)Cv;
                *(float2*)(C + (size_t)r0 * N + cc) = make_float2(v00, v01);
                *(float2*)(C + (size_t)r1 * N + cc) = make_float2(v10, v11);
            } else if (EPI == 1) {
                bf16* C = (bf16*)Cv;
                *(bf162*)(C + (size_t)r0 * N + cc) =
                    __floats2bfloat162_rn(gelu_tanh(v00), gelu_tanh(v01));
                *(bf162*)(C + (size_t)r1 * N + cc) =
                    __floats2bfloat162_rn(gelu_tanh(v10), gelu_tanh(v11));
            } else {
                float* C = (float*)Cv;
                float* p0 = C + (size_t)r0 * N + cc;
                float* p1 = C + (size_t)r1 * N + cc;
                float2 o0 = *(float2*)p0, o1 = *(float2*)p1;
                *(float2*)p0 = make_float2(o0.x + v00, o0.y + v01);
                *(float2*)p1 = make_float2(o1.x + v10, o1.y + v11);
            }
        }
    }
}

// ---------------------------------------------------------------------------
// kernel_launch
// ---------------------------------------------------------------------------
extern "C" void kernel_launch(void* const* d_in, const int* in_sizes, int n_in,
                              void* d_out, int out_size) {
    const float* x      = (const float*)d_in[0];
    const float* cosT   = (const float*)d_in[1];
    const float* sinT   = (const float*)d_in[2];
    const float* qkv_w  = (const float*)d_in[3];
    const float* qkv_b  = (const float*)d_in[4];
    const float* nq_s   = (const float*)d_in[5];
    const float* nk_s   = (const float*)d_in[6];
    const float* proj_w = (const float*)d_in[7];
    const float* proj_b = (const float*)d_in[8];
    const float* n1_s   = (const float*)d_in[9];
    const float* n2_s   = (const float*)d_in[10];
    const float* w1     = (const float*)d_in[11];
    const float* b1     = (const float*)d_in[12];
    const float* w2     = (const float*)d_in[13];
    const float* b2     = (const float*)d_in[14];
    float* out = (float*)d_out;

    float *xs, *qkv, *ysum;
    bf16 *xnb, *ysb, *hb, *h1b, *wq, *wp, *ww1, *ww2;
    cudaGetSymbolAddress((void**)&xs,   g_xs);
    cudaGetSymbolAddress((void**)&xnb,  g_xnb);
    cudaGetSymbolAddress((void**)&qkv,  g_qkv);
    cudaGetSymbolAddress((void**)&ysum, g_ysum);
    cudaGetSymbolAddress((void**)&ysb,  g_ysb);
    cudaGetSymbolAddress((void**)&hb,   g_hb);
    cudaGetSymbolAddress((void**)&h1b,  g_h1b);
    cudaGetSymbolAddress((void**)&wq,   g_wqkv);
    cudaGetSymbolAddress((void**)&wp,   g_wproj);
    cudaGetSymbolAddress((void**)&ww1,  g_w1);
    cudaGetSymbolAddress((void**)&ww2,  g_w2);

    cudaFuncSetAttribute(mma_gemm<0>, cudaFuncAttributeMaxDynamicSharedMemorySize, GEMM_SMEM_BYTES);
    cudaFuncSetAttribute(mma_gemm<1>, cudaFuncAttributeMaxDynamicSharedMemorySize, GEMM_SMEM_BYTES);
    cudaFuncSetAttribute(mma_gemm<2>, cudaFuncAttributeMaxDynamicSharedMemorySize, GEMM_SMEM_BYTES);

    dim3 tb(32, 8);

    // weight prep
    wprep_kernel<<<dim3(QKVN/32, DIMM/32), tb>>>(qkv_w, wq, DIMM, QKVN);
    wprep_kernel<<<dim3(DIMM/32, DIMM/32), tb>>>(proj_w, wp, DIMM, DIMM);
    wprep_kernel<<<dim3(FFN/32,  DIMM/32), tb>>>(w1, ww1, DIMM, FFN);
    wprep_kernel<<<dim3(DIMM/32, FFN/32),  tb>>>(w2, ww2, FFN, DIMM);

    // fused transpose + rms1
    fuse_in_kernel<<<dim3(LL/16, BB), 256>>>(x, n1_s, xs, xnb);

    // qkv = xnb @ wq^T + qkv_b
    mma_gemm<0><<<dim3(QKVN/GBN, NTOK/GBM), 256, GEMM_SMEM_BYTES>>>(
        xnb, wq, qkv_b, qkv, NTOK, QKVN, DIMM);

    // q/k rmsnorm + rope
    qkrope_kernel<<<NTOK/4, 128>>>(qkv, nq_s, nk_s, cosT, sinT);

    // three attentions
    attn_kernel<0, 64,  0><<<dim3(BB * TT,  NHEAD), 64 >>>(qkv, ysum, ysb);
    attn_kernel<1, 128, 1><<<dim3(BB * FRR, NHEAD), 128>>>(qkv, ysum, ysb);
    attn_kernel<2, 32,  2><<<dim3(BB * 256, NHEAD), 32 >>>(qkv, ysum, ysb);

    // xs += ysb @ wp^T + proj_b
    mma_gemm<2><<<dim3(DIMM/GBN, NTOK/GBM), 256, GEMM_SMEM_BYTES>>>(
        ysb, wp, proj_b, xs, NTOK, DIMM, DIMM);

    // hb = bf16(rms(xs, n2))
    rms_kernel<<<NTOK, 128>>>(xs, n2_s, hb);

    // h1b = bf16(gelu(hb @ ww1^T + b1))
    mma_gemm<1><<<dim3(FFN/GBN, NTOK/GBM), 256, GEMM_SMEM_BYTES>>>(
        hb, ww1, b1, h1b, NTOK, FFN, DIMM);

    // xs += h1b @ ww2^T + b2
    mma_gemm<2><<<dim3(DIMM/GBN, NTOK/GBM), 256, GEMM_SMEM_BYTES>>>(
        h1b, ww2, b2, xs, NTOK, DIMM, FFN);

    // xs -> out
    transpose_kernel<<<dim3(DIMM/32, LL/32, BB), tb>>>(xs, out, LL, DIMM);
}

// round 13
// speedup vs baseline: 1.4848x; 1.4848x over previous
#include <cuda_runtime.h>
#include <cuda_bf16.h>
#include <math.h>
#include <stdint.h>

#define BB    4
#define TT    128
#define FRR   64
#define LL    8192
#define DIMM  384
#define NHEAD 12
#define HDIM  32
#define NTOK  (BB*LL)
#define QKVN  (3*DIMM)
#define FFN   (4*DIMM)

typedef __nv_bfloat16  bf16;
typedef __nv_bfloat162 bf162;

// ---------------------------------------------------------------------------
// Scratch
// ---------------------------------------------------------------------------
__device__ float g_xs  [(size_t)NTOK * DIMM];
__device__ bf16  g_xnb [(size_t)NTOK * DIMM];
__device__ float g_qkv [(size_t)NTOK * QKVN];
__device__ float g_ysum[(size_t)NTOK * DIMM];
__device__ bf16  g_ysb [(size_t)NTOK * DIMM];
__device__ bf16  g_hb  [(size_t)NTOK * DIMM];
__device__ bf16  g_h1b [(size_t)NTOK * FFN];
__device__ bf16  g_wqkv [QKVN * DIMM];
__device__ bf16  g_wproj[DIMM * DIMM];
__device__ bf16  g_w1   [FFN * DIMM];
__device__ bf16  g_w2   [DIMM * FFN];

// ---------------------------------------------------------------------------
// common PTX helpers
// ---------------------------------------------------------------------------
__device__ __forceinline__ void cp16(uint32_t smem, const void* gmem) {
    asm volatile("cp.async.cg.shared.global [%0], [%1], 16;\n" :: "r"(smem), "l"(gmem));
}
#define CP_COMMIT() asm volatile("cp.async.commit_group;\n" ::: "memory")
#define CP_WAIT(n)  asm volatile("cp.async.wait_group %0;\n" :: "n"(n) : "memory")

__device__ __forceinline__ void ldsm4(unsigned& r0, unsigned& r1,
                                      unsigned& r2, unsigned& r3, unsigned addr) {
    asm volatile("ldmatrix.sync.aligned.m8n8.x4.shared.b16 {%0,%1,%2,%3}, [%4];\n"
                 : "=r"(r0), "=r"(r1), "=r"(r2), "=r"(r3) : "r"(addr));
}

__device__ __forceinline__ void mma_bf16(float* c, const unsigned* a, const unsigned* b) {
    asm volatile(
        "mma.sync.aligned.m16n8k16.row.col.f32.bf16.bf16.f32 "
        "{%0,%1,%2,%3}, {%4,%5,%6,%7}, {%8,%9}, {%0,%1,%2,%3};\n"
        : "+f"(c[0]), "+f"(c[1]), "+f"(c[2]), "+f"(c[3])
        : "r"(a[0]), "r"(a[1]), "r"(a[2]), "r"(a[3]), "r"(b[0]), "r"(b[1]));
}

__device__ __forceinline__ unsigned packbf(float lo, float hi) {
    bf162 v = __floats2bfloat162_rn(lo, hi);
    unsigned u;
    memcpy(&u, &v, 4);
    return u;
}

__device__ __forceinline__ float gelu_tanh(float x) {
    float c = 0.7978845608028654f;
    float t = tanhf(c * (x + 0.044715f * x * x * x));
    return 0.5f * x * (1.0f + t);
}

// ---------------------------------------------------------------------------
// Weight prep: w [K][N] f32 -> wt [N][K] bf16
// ---------------------------------------------------------------------------
__global__ void wprep_kernel(const float* __restrict__ w,
                             bf16* __restrict__ wt, int K, int N) {
    __shared__ float tile[32][33];
    int n0 = blockIdx.x * 32, k0 = blockIdx.y * 32;
    int tx = threadIdx.x, ty = threadIdx.y;
    #pragma unroll
    for (int i = 0; i < 32; i += 8)
        tile[ty + i][tx] = w[(size_t)(k0 + ty + i) * N + n0 + tx];
    __syncthreads();
    #pragma unroll
    for (int i = 0; i < 32; i += 8)
        wt[(size_t)(n0 + ty + i) * K + k0 + tx] =
            __float2bfloat16_rn(tile[tx][ty + i]);
}

// ---------------------------------------------------------------------------
// Fused input transpose + rms1
// ---------------------------------------------------------------------------
__global__ __launch_bounds__(256)
void fuse_in_kernel(const float* __restrict__ x,
                    const float* __restrict__ n1,
                    float* __restrict__ xs, bf16* __restrict__ xnb) {
    __shared__ float tile[DIMM][17];
    __shared__ float rinv[16];
    int tid = threadIdx.x;
    int l0 = blockIdx.x * 16;
    int b  = blockIdx.y;
    const float* xb = x + (size_t)b * DIMM * LL + l0;

    #pragma unroll
    for (int it = 0; it < 24; it++) {
        int idx = tid + it * 256;
        int d = idx >> 4, c = idx & 15;
        tile[d][c] = xb[(size_t)d * LL + c];
    }
    __syncthreads();

    int tok = tid >> 4, j = tid & 15;
    float s = 0.f;
    #pragma unroll
    for (int k = 0; k < 24; k++) {
        float v = tile[j + 16 * k][tok];
        s += v * v;
    }
    #pragma unroll
    for (int m = 8; m >= 1; m >>= 1)
        s += __shfl_xor_sync(0xffffffffu, s, m);
    if (j == 0) rinv[tok] = rsqrtf(s * (1.0f / DIMM) + 1e-6f);
    __syncthreads();

    size_t gbase = ((size_t)b * LL + l0) * DIMM;
    #pragma unroll
    for (int it = 0; it < 24; it++) {
        int idx = tid + it * 256;
        int t2 = idx / DIMM, d = idx - t2 * DIMM;
        float raw = tile[d][t2];
        xs[gbase + (size_t)t2 * DIMM + d] = raw;
        xnb[gbase + (size_t)t2 * DIMM + d] =
            __float2bfloat16_rn(raw * rinv[t2] * n1[d]);
    }
}

// ---------------------------------------------------------------------------
// Output transpose
// ---------------------------------------------------------------------------
__global__ void transpose_kernel(const float* __restrict__ in,
                                 float* __restrict__ out,
                                 int rows, int cols) {
    __shared__ float tile[32][33];
    int bx = blockIdx.x * 32;
    int by = blockIdx.y * 32;
    size_t plane = (size_t)rows * cols;
    const float* inb = in + (size_t)blockIdx.z * plane;
    float* outb      = out + (size_t)blockIdx.z * plane;
    int tx = threadIdx.x, ty = threadIdx.y;
    #pragma unroll
    for (int i = 0; i < 32; i += 8)
        tile[ty + i][tx] = inb[(size_t)(by + ty + i) * cols + bx + tx];
    __syncthreads();
    #pragma unroll
    for (int i = 0; i < 32; i += 8)
        outb[(size_t)(bx + ty + i) * rows + by + tx] = tile[tx][ty + i];
}

// ---------------------------------------------------------------------------
// rms2
// ---------------------------------------------------------------------------
__global__ void rms_kernel(const float* __restrict__ in,
                           const float* __restrict__ scale,
                           bf16* __restrict__ out) {
    int tok = blockIdx.x;
    int tid = threadIdx.x;
    const float* row = in + (size_t)tok * DIMM;
    float v0 = row[tid], v1 = row[tid + 128], v2 = row[tid + 256];
    float s = v0*v0 + v1*v1 + v2*v2;
    #pragma unroll
    for (int off = 16; off > 0; off >>= 1)
        s += __shfl_down_sync(0xffffffffu, s, off);
    __shared__ float red[4];
    if ((tid & 31) == 0) red[tid >> 5] = s;
    __syncthreads();
    if (tid == 0) {
        float t = red[0] + red[1] + red[2] + red[3];
        red[0] = rsqrtf(t * (1.0f / DIMM) + 1e-6f);
    }
    __syncthreads();
    float rinv = red[0];
    bf16* orow = out + (size_t)tok * DIMM;
    orow[tid]       = __float2bfloat16_rn(v0 * rinv * scale[tid]);
    orow[tid + 128] = __float2bfloat16_rn(v1 * rinv * scale[tid + 128]);
    orow[tid + 256] = __float2bfloat16_rn(v2 * rinv * scale[tid + 256]);
}

// ---------------------------------------------------------------------------
// QK rms-norm + RoPE
// ---------------------------------------------------------------------------
__global__ __launch_bounds__(128)
void qkrope_kernel(float* __restrict__ qkv,
                   const float* __restrict__ nq,
                   const float* __restrict__ nk,
                   const float* __restrict__ cosT,
                   const float* __restrict__ sinT) {
    int tid = threadIdx.x;
    int lane = tid & 31;
    int tok = blockIdx.x * 4 + (tid >> 5);
    size_t base = (size_t)tok * QKVN;
    float* qp = qkv + base;
    float* kp = qkv + base + DIMM;

    float4 qv[3], kv[3];
    float ssq = 0.f, ssk = 0.f;
    #pragma unroll
    for (int i = 0; i < 3; i++) {
        int e0 = i * 128 + lane * 4;
        qv[i] = *(const float4*)(qp + e0);
        kv[i] = *(const float4*)(kp + e0);
        ssq += qv[i].x*qv[i].x + qv[i].y*qv[i].y + qv[i].z*qv[i].z + qv[i].w*qv[i].w;
        ssk += kv[i].x*kv[i].x + kv[i].y*kv[i].y + kv[i].z*kv[i].z + kv[i].w*kv[i].w;
    }
    #pragma unroll
    for (int m = 16; m >= 1; m >>= 1) {
        ssq += __shfl_xor_sync(0xffffffffu, ssq, m);
        ssk += __shfl_xor_sync(0xffffffffu, ssk, m);
    }
    float rq = rsqrtf(ssq * (1.0f / DIMM) + 1e-6f);
    float rk = rsqrtf(ssk * (1.0f / DIMM) + 1e-6f);

    int l = tok & (LL - 1);
    int j2 = 2 * (lane & 7);
    float c0 = cosT[l * 16 + j2],     s0 = sinT[l * 16 + j2];
    float c1 = cosT[l * 16 + j2 + 1], s1 = sinT[l * 16 + j2 + 1];

    #pragma unroll
    for (int i = 0; i < 3; i++) {
        int e0 = i * 128 + lane * 4;
        float4 nqv = *(const float4*)(nq + e0);
        float4 nkv = *(const float4*)(nk + e0);
        float a0 = qv[i].x * rq * nqv.x, a1 = qv[i].y * rq * nqv.y;
        float a2 = qv[i].z * rq * nqv.z, a3 = qv[i].w * rq * nqv.w;
        float4 o;
        o.x = a0 * c0 - a1 * s0;  o.y = a0 * s0 + a1 * c0;
        o.z = a2 * c1 - a3 * s1;  o.w = a2 * s1 + a3 * c1;
        *(float4*)(qp + e0) = o;
        float b0 = kv[i].x * rk * nkv.x, b1 = kv[i].y * rk * nkv.y;
        float b2 = kv[i].z * rk * nkv.z, b3 = kv[i].w * rk * nkv.w;
        float4 p;
        p.x = b0 * c0 - b1 * s0;  p.y = b0 * s0 + b1 * c0;
        p.z = b2 * c1 - b3 * s1;  p.w = b2 * s1 + b3 * c1;
        *(float4*)(kp + e0) = p;
    }
}

// ---------------------------------------------------------------------------
// Tensor-core attention: warp-per-(group,head), bf16 mma, fp32 softmax.
// S in {32,64,128}. 4 warps/CTA. grid: (groups/4, NHEAD).
// MODE 0: ysum = y;  MODE 1: ysum += y;  MODE 2: ysum += y and ysb = bf16(ysum)
// ---------------------------------------------------------------------------
template <int VAR>
__device__ __forceinline__ int tok_of(int g, int s) {
    if (VAR == 0) { int b = g >> 7, t = g & 127; return b * LL + t * FRR + s; }
    if (VAR == 1) { int b = g >> 6, fr = g & 63; return b * LL + s * FRR + fr; }
    int b = g >> 8, r = g & 255;
    int t1 = r >> 3, f1 = r & 7;
    int t2 = s >> 3, f2 = s & 7;
    return b * LL + (t1 * 4 + t2) * FRR + f1 * 8 + f2;
}

template <int VAR, int S, int MODE>
__global__ __launch_bounds__(128)
void attn_mma(const float* __restrict__ qkv,
              float* __restrict__ ysum, bf16* __restrict__ ysb) {
    extern __shared__ char asmem[];
    constexpr int QSTR = 40;          // bf16 row stride for Q,K tiles
    constexpr int VSTR = S + 8;       // bf16 row stride for Vt tile
    constexpr int QSZ  = S * QSTR;    // elems
    constexpr int VTSZ = 32 * VSTR;
    constexpr int JOB  = 2 * QSZ + VTSZ;

    int tid = threadIdx.x, wid = tid >> 5, lane = tid & 31;
    int g = blockIdx.x * 4 + wid;
    int h = blockIdx.y;

    bf16* Qs = (bf16*)asmem + (size_t)wid * JOB;
    bf16* Ks = Qs + QSZ;
    bf16* Vt = Ks + QSZ;

    // ---- stage Q, K, Vt (bf16) ----
    for (int j = 0; j < S; j++) {
        size_t base = (size_t)tok_of<VAR>(g, j) * QKVN + h * HDIM + lane;
        Qs[j * QSTR + lane] = __float2bfloat16_rn(qkv[base]);
        Ks[j * QSTR + lane] = __float2bfloat16_rn(qkv[base + 384]);
        Vt[lane * VSTR + j] = __float2bfloat16_rn(qkv[base + 768]);
    }
    __syncwarp();

    uint32_t Qu = (uint32_t)__cvta_generic_to_shared(Qs);
    uint32_t Ku = (uint32_t)__cvta_generic_to_shared(Ks);
    uint32_t Vu = (uint32_t)__cvta_generic_to_shared(Vt);

    int mrow = lane & 7, sel = lane >> 3;
    int a_row = (sel & 1) * 8 + mrow, a_k = (sel >> 1) * 8;
    int b_row = (sel >> 1) * 8 + mrow, b_k = (sel & 1) * 8;
    int gid = lane >> 2, tid4 = lane & 3;
    const float rscale = 0.17677669529663687f;

    for (int mt = 0; mt < S / 16; mt++) {
        // Q A-frags for this 16-row chunk (k = 32 -> 2 k-steps)
        unsigned aq[2][4];
        #pragma unroll
        for (int ks = 0; ks < 2; ks++) {
            uint32_t addr = Qu +
                (uint32_t)((mt * 16 + a_row) * QSTR + ks * 16 + a_k) * 2;
            ldsm4(aq[ks][0], aq[ks][1], aq[ks][2], aq[ks][3], addr);
        }

        float cy[4][4];
        #pragma unroll
        for (int nt = 0; nt < 4; nt++)
            #pragma unroll
            for (int r = 0; r < 4; r++) cy[nt][r] = 0.f;
        float ls0 = 0.f, ls1 = 0.f;

        for (int jt = 0; jt < S / 16; jt++) {
            // K B-frags: 2 k-steps x 2 n8-tiles
            unsigned bk[2][2][2];
            #pragma unroll
            for (int ks = 0; ks < 2; ks++) {
                uint32_t addr = Ku +
                    (uint32_t)((jt * 16 + b_row) * QSTR + ks * 16 + b_k) * 2;
                ldsm4(bk[ks][0][0], bk[ks][0][1], bk[ks][1][0], bk[ks][1][1], addr);
            }
            // scores 16x16
            float sc[2][4];
            #pragma unroll
            for (int nt = 0; nt < 2; nt++)
                #pragma unroll
                for (int r = 0; r < 4; r++) sc[nt][r] = 0.f;
            #pragma unroll
            for (int ks = 0; ks < 2; ks++)
                #pragma unroll
                for (int nt = 0; nt < 2; nt++)
                    mma_bf16(sc[nt], aq[ks], bk[ks][nt]);

            // softmax numerators (no max needed: scores bounded)
            float p00 = __expf(sc[0][0] * rscale), p01 = __expf(sc[0][1] * rscale);
            float p02 = __expf(sc[0][2] * rscale), p03 = __expf(sc[0][3] * rscale);
            float p10 = __expf(sc[1][0] * rscale), p11 = __expf(sc[1][1] * rscale);
            float p12 = __expf(sc[1][2] * rscale), p13 = __expf(sc[1][3] * rscale);
            ls0 += p00 + p01 + p10 + p11;     // row r
            ls1 += p02 + p03 + p12 + p13;     // row r+8
            // repack P accum frags -> A frag (m16 k16)
            unsigned pa[4];
            pa[0] = packbf(p00, p01);
            pa[1] = packbf(p02, p03);
            pa[2] = packbf(p10, p11);
            pa[3] = packbf(p12, p13);

            // Vt B-frags: 4 n8-tiles (d = 0..31), k = this 16-key chunk
            unsigned bv[4][2];
            #pragma unroll
            for (int np = 0; np < 2; np++) {
                uint32_t addr = Vu +
                    (uint32_t)((np * 16 + b_row) * VSTR + jt * 16 + b_k) * 2;
                ldsm4(bv[2*np][0], bv[2*np][1], bv[2*np+1][0], bv[2*np+1][1], addr);
            }
            #pragma unroll
            for (int nt = 0; nt < 4; nt++)
                mma_bf16(cy[nt], pa, bv[nt]);
        }

        // full row sums across the quad (lanes sharing gid)
        ls0 += __shfl_xor_sync(0xffffffffu, ls0, 1);
        ls0 += __shfl_xor_sync(0xffffffffu, ls0, 2);
        ls1 += __shfl_xor_sync(0xffffffffu, ls1, 1);
        ls1 += __shfl_xor_sync(0xffffffffu, ls1, 2);
        float inv0 = 1.f / ls0, inv1 = 1.f / ls1;

        int r0 = mt * 16 + gid, r1 = r0 + 8;
        size_t o0 = (size_t)tok_of<VAR>(g, r0) * DIMM + h * HDIM;
        size_t o1 = (size_t)tok_of<VAR>(g, r1) * DIMM + h * HDIM;
        #pragma unroll
        for (int nt = 0; nt < 4; nt++) {
            int cc = nt * 8 + 2 * tid4;
            float v00 = cy[nt][0] * inv0, v01 = cy[nt][1] * inv0;
            float v10 = cy[nt][2] * inv1, v11 = cy[nt][3] * inv1;
            float* p0 = ysum + o0 + cc;
            float* p1 = ysum + o1 + cc;
            if (MODE == 0) {
                *(float2*)p0 = make_float2(v00, v01);
                *(float2*)p1 = make_float2(v10, v11);
            } else if (MODE == 1) {
                float2 a0 = *(float2*)p0, a1 = *(float2*)p1;
                *(float2*)p0 = make_float2(a0.x + v00, a0.y + v01);
                *(float2*)p1 = make_float2(a1.x + v10, a1.y + v11);
            } else {
                float2 a0 = *(float2*)p0, a1 = *(float2*)p1;
                float t00 = a0.x + v00, t01 = a0.y + v01;
                float t10 = a1.x + v10, t11 = a1.y + v11;
                *(float2*)p0 = make_float2(t00, t01);
                *(float2*)p1 = make_float2(t10, t11);
                *(bf162*)(ysb + o0 + cc) = __floats2bfloat162_rn(t00, t01);
                *(bf162*)(ysb + o1 + cc) = __floats2bfloat162_rn(t10, t11);
            }
        }
    }
}

#define ATTN_SMEM(S) (4 * (2 * (S) * 40 + 32 * ((S) + 8)) * 2)

// ---------------------------------------------------------------------------
// bf16 mma.sync GEMM (R8-identical: 2-stage cp.async, ldmatrix, GBK=64)
// ---------------------------------------------------------------------------
#define GBM 128
#define GBN 128
#define GBK 64
#define KSTR 72
#define ATILE (2 * GBM * KSTR)
#define GEMM_SMEM_BYTES (2 * ATILE * 2)

template <int EPI>
__global__ __launch_bounds__(256)
void mma_gemm(const bf16* __restrict__ A, const bf16* __restrict__ Wt,
              const float* __restrict__ bias, void* __restrict__ Cv,
              int M, int N, int K) {
    extern __shared__ char dynsmem[];
    bf16* As = (bf16*)dynsmem;
    bf16* Bs = (bf16*)(dynsmem + ATILE * 2);

    int tid  = threadIdx.x;
    int n0   = blockIdx.x * GBN, m0 = blockIdx.y * GBM;
    int warp = tid >> 5, lane = tid & 31;
    int wm   = (warp & 3) * 32;
    int wn   = (warp >> 2) * 64;

    const bf16* Abase = A  + (size_t)m0 * K;
    const bf16* Bbase = Wt + (size_t)n0 * K;

    int mrow = lane & 7;
    int sel  = lane >> 3;
    int a_row_add = (sel & 1) * 8 + mrow;
    int a_k_add   = (sel >> 1) * 8;
    int b_row_add = (sel >> 1) * 8 + mrow;
    int b_k_add   = (sel & 1) * 8;

    uint32_t As_u = (uint32_t)__cvta_generic_to_shared(As);
    uint32_t Bs_u = (uint32_t)__cvta_generic_to_shared(Bs);

    float c[2][8][4];
    #pragma unroll
    for (int mt = 0; mt < 2; mt++)
        #pragma unroll
        for (int nt = 0; nt < 8; nt++)
            #pragma unroll
            for (int r = 0; r < 4; r++) c[mt][nt][r] = 0.f;

    auto load_tiles = [&](int buf, int k0) {
        bf16* Ad = As + buf * GBM * KSTR;
        bf16* Bd = Bs + buf * GBN * KSTR;
        #pragma unroll
        for (int i = 0; i < 4; i++) {
            int ch = tid + i * 256;
            int r = ch >> 3, cc = ch & 7;
            cp16((uint32_t)__cvta_generic_to_shared(Ad + r * KSTR + cc * 8),
                 Abase + (size_t)r * K + k0 + cc * 8);
            cp16((uint32_t)__cvta_generic_to_shared(Bd + r * KSTR + cc * 8),
                 Bbase + (size_t)r * K + k0 + cc * 8);
        }
    };

    int kTiles = K / GBK;
    load_tiles(0, 0);
    CP_COMMIT();

    for (int kt = 0; kt < kTiles; kt++) {
        int buf = kt & 1;
        if (kt + 1 < kTiles) {
            load_tiles(buf ^ 1, (kt + 1) * GBK);
            CP_COMMIT();
            CP_WAIT(1);
        } else {
            CP_WAIT(0);
        }
        __syncthreads();

        uint32_t Abuf = As_u + (uint32_t)(buf * GBM * KSTR) * 2;
        uint32_t Bbuf = Bs_u + (uint32_t)(buf * GBN * KSTR) * 2;

        #pragma unroll
        for (int ks = 0; ks < GBK; ks += 16) {
            unsigned af[2][4], bfr[8][2];
            #pragma unroll
            for (int mt = 0; mt < 2; mt++) {
                uint32_t addr = Abuf +
                    (uint32_t)((wm + mt * 16 + a_row_add) * KSTR + ks + a_k_add) * 2;
                ldsm4(af[mt][0], af[mt][1], af[mt][2], af[mt][3], addr);
            }
            #pragma unroll
            for (int np = 0; np < 4; np++) {
                uint32_t addr = Bbuf +
                    (uint32_t)((wn + np * 16 + b_row_add) * KSTR + ks + b_k_add) * 2;
                ldsm4(bfr[2*np][0], bfr[2*np][1], bfr[2*np+1][0], bfr[2*np+1][1], addr);
            }
            #pragma unroll
            for (int mt = 0; mt < 2; mt++)
                #pragma unroll
                for (int nt = 0; nt < 8; nt++)
                    mma_bf16(c[mt][nt], af[mt], bfr[nt]);
        }
        __syncthreads();
    }

    int gid  = lane >> 2, tid4 = lane & 3;
    #pragma unroll
    for (int mt = 0; mt < 2; mt++) {
        int r0 = m0 + wm + mt * 16 + gid;
        int r1 = r0 + 8;
        #pragma unroll
        for (int nt = 0; nt < 8; nt++) {
            int cc = n0 + wn + nt * 8 + 2 * tid4;
            float b0 = bias[cc], b1 = bias[cc + 1];
            float v00 = c[mt][nt][0] + b0, v01 = c[mt][nt][1] + b1;
            float v10 = c[mt][nt][2] + b0, v11 = c[mt][nt][3] + b1;
            if (EPI == 0) {
                float* C = (float*)Cv;
                *(float2*)(C + (size_t)r0 * N + cc) = make_float2(v00, v01);
                *(float2*)(C + (size_t)r1 * N + cc) = make_float2(v10, v11);
            } else if (EPI == 1) {
                bf16* C = (bf16*)Cv;
                *(bf162*)(C + (size_t)r0 * N + cc) =
                    __floats2bfloat162_rn(gelu_tanh(v00), gelu_tanh(v01));
                *(bf162*)(C + (size_t)r1 * N + cc) =
                    __floats2bfloat162_rn(gelu_tanh(v10), gelu_tanh(v11));
            } else {
                float* C = (float*)Cv;
                float* p0 = C + (size_t)r0 * N + cc;
                float* p1 = C + (size_t)r1 * N + cc;
                float2 o0 = *(float2*)p0, o1 = *(float2*)p1;
                *(float2*)p0 = make_float2(o0.x + v00, o0.y + v01);
                *(float2*)p1 = make_float2(o1.x + v10, o1.y + v11);
            }
        }
    }
}

// ---------------------------------------------------------------------------
// kernel_launch
// ---------------------------------------------------------------------------
extern "C" void kernel_launch(void* const* d_in, const int* in_sizes, int n_in,
                              void* d_out, int out_size) {
    const float* x      = (const float*)d_in[0];
    const float* cosT   = (const float*)d_in[1];
    const float* sinT   = (const float*)d_in[2];
    const float* qkv_w  = (const float*)d_in[3];
    const float* qkv_b  = (const float*)d_in[4];
    const float* nq_s   = (const float*)d_in[5];
    const float* nk_s   = (const float*)d_in[6];
    const float* proj_w = (const float*)d_in[7];
    const float* proj_b = (const float*)d_in[8];
    const float* n1_s   = (const float*)d_in[9];
    const float* n2_s   = (const float*)d_in[10];
    const float* w1     = (const float*)d_in[11];
    const float* b1     = (const float*)d_in[12];
    const float* w2     = (const float*)d_in[13];
    const float* b2     = (const float*)d_in[14];
    float* out = (float*)d_out;

    float *xs, *qkv, *ysum;
    bf16 *xnb, *ysb, *hb, *h1b, *wq, *wp, *ww1, *ww2;
    cudaGetSymbolAddress((void**)&xs,   g_xs);
    cudaGetSymbolAddress((void**)&xnb,  g_xnb);
    cudaGetSymbolAddress((void**)&qkv,  g_qkv);
    cudaGetSymbolAddress((void**)&ysum, g_ysum);
    cudaGetSymbolAddress((void**)&ysb,  g_ysb);
    cudaGetSymbolAddress((void**)&hb,   g_hb);
    cudaGetSymbolAddress((void**)&h1b,  g_h1b);
    cudaGetSymbolAddress((void**)&wq,   g_wqkv);
    cudaGetSymbolAddress((void**)&wp,   g_wproj);
    cudaGetSymbolAddress((void**)&ww1,  g_w1);
    cudaGetSymbolAddress((void**)&ww2,  g_w2);

    cudaFuncSetAttribute(mma_gemm<0>, cudaFuncAttributeMaxDynamicSharedMemorySize, GEMM_SMEM_BYTES);
    cudaFuncSetAttribute(mma_gemm<1>, cudaFuncAttributeMaxDynamicSharedMemorySize, GEMM_SMEM_BYTES);
    cudaFuncSetAttribute(mma_gemm<2>, cudaFuncAttributeMaxDynamicSharedMemorySize, GEMM_SMEM_BYTES);
    cudaFuncSetAttribute(attn_mma<0, 64, 0>, cudaFuncAttributeMaxDynamicSharedMemorySize, ATTN_SMEM(64));
    cudaFuncSetAttribute(attn_mma<1, 128, 1>, cudaFuncAttributeMaxDynamicSharedMemorySize, ATTN_SMEM(128));
    cudaFuncSetAttribute(attn_mma<2, 32, 2>, cudaFuncAttributeMaxDynamicSharedMemorySize, ATTN_SMEM(32));

    dim3 tb(32, 8);

    // weight prep
    wprep_kernel<<<dim3(QKVN/32, DIMM/32), tb>>>(qkv_w, wq, DIMM, QKVN);
    wprep_kernel<<<dim3(DIMM/32, DIMM/32), tb>>>(proj_w, wp, DIMM, DIMM);
    wprep_kernel<<<dim3(FFN/32,  DIMM/32), tb>>>(w1, ww1, DIMM, FFN);
    wprep_kernel<<<dim3(DIMM/32, FFN/32),  tb>>>(w2, ww2, FFN, DIMM);

    // fused transpose + rms1
    fuse_in_kernel<<<dim3(LL/16, BB), 256>>>(x, n1_s, xs, xnb);

    // qkv = xnb @ wq^T + qkv_b
    mma_gemm<0><<<dim3(QKVN/GBN, NTOK/GBM), 256, GEMM_SMEM_BYTES>>>(
        xnb, wq, qkv_b, qkv, NTOK, QKVN, DIMM);

    // q/k rmsnorm + rope
    qkrope_kernel<<<NTOK/4, 128>>>(qkv, nq_s, nk_s, cosT, sinT);

    // three attentions (tensor-core)
    attn_mma<0, 64,  0><<<dim3(BB * TT / 4,  NHEAD), 128, ATTN_SMEM(64)>>>(qkv, ysum, ysb);
    attn_mma<1, 128, 1><<<dim3(BB * FRR / 4, NHEAD), 128, ATTN_SMEM(128)>>>(qkv, ysum, ysb);
    attn_mma<2, 32,  2><<<dim3(BB * 256 / 4, NHEAD), 128, ATTN_SMEM(32)>>>(qkv, ysum, ysb);

    // xs += ysb @ wp^T + proj_b
    mma_gemm<2><<<dim3(DIMM/GBN, NTOK/GBM), 256, GEMM_SMEM_BYTES>>>(
        ysb, wp, proj_b, xs, NTOK, DIMM, DIMM);

    // hb = bf16(rms(xs, n2))
    rms_kernel<<<NTOK, 128>>>(xs, n2_s, hb);

    // h1b = bf16(gelu(hb @ ww1^T + b1))
    mma_gemm<1><<<dim3(FFN/GBN, NTOK/GBM), 256, GEMM_SMEM_BYTES>>>(
        hb, ww1, b1, h1b, NTOK, FFN, DIMM);

    // xs += h1b @ ww2^T + b2
    mma_gemm<2><<<dim3(DIMM/GBN, NTOK/GBM), 256, GEMM_SMEM_BYTES>>>(
        h1b, ww2, b2, xs, NTOK, DIMM, FFN);

    // xs -> out
    transpose_kernel<<<dim3(DIMM/32, LL/32, BB), tb>>>(xs, out, LL, DIMM);
}

// round 14
// speedup vs baseline: 1.7336x; 1.1675x over previous
#include <cuda_runtime.h>
#include <cuda_bf16.h>
#include <math.h>
#include <stdint.h>

#define BB    4
#define TT    128
#define FRR   64
#define LL    8192
#define DIMM  384
#define NHEAD 12
#define HDIM  32
#define NTOK  (BB*LL)
#define QKVN  (3*DIMM)
#define FFN   (4*DIMM)

typedef __nv_bfloat16  bf16;
typedef __nv_bfloat162 bf162;

// ---------------------------------------------------------------------------
// Scratch
// ---------------------------------------------------------------------------
__device__ float g_xs  [(size_t)NTOK * DIMM];
__device__ bf16  g_xnb [(size_t)NTOK * DIMM];
__device__ bf16  g_qkvb[(size_t)NTOK * QKVN];   // bf16 qkv
__device__ float g_ysum[(size_t)NTOK * DIMM];
__device__ bf16  g_ysb [(size_t)NTOK * DIMM];
__device__ bf16  g_hb  [(size_t)NTOK * DIMM];
__device__ bf16  g_h1b [(size_t)NTOK * FFN];
__device__ bf16  g_wqkv [QKVN * DIMM];
__device__ bf16  g_wproj[DIMM * DIMM];
__device__ bf16  g_w1   [FFN * DIMM];
__device__ bf16  g_w2   [DIMM * FFN];

// ---------------------------------------------------------------------------
// common PTX helpers
// ---------------------------------------------------------------------------
__device__ __forceinline__ void cp16(uint32_t smem, const void* gmem) {
    asm volatile("cp.async.cg.shared.global [%0], [%1], 16;\n" :: "r"(smem), "l"(gmem));
}
#define CP_COMMIT() asm volatile("cp.async.commit_group;\n" ::: "memory")
#define CP_WAIT(n)  asm volatile("cp.async.wait_group %0;\n" :: "n"(n) : "memory")

__device__ __forceinline__ void ldsm4(unsigned& r0, unsigned& r1,
                                      unsigned& r2, unsigned& r3, unsigned addr) {
    asm volatile("ldmatrix.sync.aligned.m8n8.x4.shared.b16 {%0,%1,%2,%3}, [%4];\n"
                 : "=r"(r0), "=r"(r1), "=r"(r2), "=r"(r3) : "r"(addr));
}

__device__ __forceinline__ void mma_bf16(float* c, const unsigned* a, const unsigned* b) {
    asm volatile(
        "mma.sync.aligned.m16n8k16.row.col.f32.bf16.bf16.f32 "
        "{%0,%1,%2,%3}, {%4,%5,%6,%7}, {%8,%9}, {%0,%1,%2,%3};\n"
        : "+f"(c[0]), "+f"(c[1]), "+f"(c[2]), "+f"(c[3])
        : "r"(a[0]), "r"(a[1]), "r"(a[2]), "r"(a[3]), "r"(b[0]), "r"(b[1]));
}

__device__ __forceinline__ unsigned packbf(float lo, float hi) {
    bf162 v = __floats2bfloat162_rn(lo, hi);
    unsigned u;
    memcpy(&u, &v, 4);
    return u;
}

__device__ __forceinline__ float2 unpackbf(unsigned u) {
    bf162 v;
    memcpy(&v, &u, 4);
    return __bfloat1622float2(v);
}

__device__ __forceinline__ float gelu_tanh(float x) {
    float c = 0.7978845608028654f;
    float t = tanhf(c * (x + 0.044715f * x * x * x));
    return 0.5f * x * (1.0f + t);
}

// ---------------------------------------------------------------------------
// Weight prep: w [K][N] f32 -> wt [N][K] bf16
// ---------------------------------------------------------------------------
__global__ void wprep_kernel(const float* __restrict__ w,
                             bf16* __restrict__ wt, int K, int N) {
    __shared__ float tile[32][33];
    int n0 = blockIdx.x * 32, k0 = blockIdx.y * 32;
    int tx = threadIdx.x, ty = threadIdx.y;
    #pragma unroll
    for (int i = 0; i < 32; i += 8)
        tile[ty + i][tx] = w[(size_t)(k0 + ty + i) * N + n0 + tx];
    __syncthreads();
    #pragma unroll
    for (int i = 0; i < 32; i += 8)
        wt[(size_t)(n0 + ty + i) * K + k0 + tx] =
            __float2bfloat16_rn(tile[tx][ty + i]);
}

// ---------------------------------------------------------------------------
// Fused input transpose + rms1
// ---------------------------------------------------------------------------
__global__ __launch_bounds__(256)
void fuse_in_kernel(const float* __restrict__ x,
                    const float* __restrict__ n1,
                    float* __restrict__ xs, bf16* __restrict__ xnb) {
    __shared__ float tile[DIMM][17];
    __shared__ float rinv[16];
    int tid = threadIdx.x;
    int l0 = blockIdx.x * 16;
    int b  = blockIdx.y;
    const float* xb = x + (size_t)b * DIMM * LL + l0;

    #pragma unroll
    for (int it = 0; it < 24; it++) {
        int idx = tid + it * 256;
        int d = idx >> 4, c = idx & 15;
        tile[d][c] = xb[(size_t)d * LL + c];
    }
    __syncthreads();

    int tok = tid >> 4, j = tid & 15;
    float s = 0.f;
    #pragma unroll
    for (int k = 0; k < 24; k++) {
        float v = tile[j + 16 * k][tok];
        s += v * v;
    }
    #pragma unroll
    for (int m = 8; m >= 1; m >>= 1)
        s += __shfl_xor_sync(0xffffffffu, s, m);
    if (j == 0) rinv[tok] = rsqrtf(s * (1.0f / DIMM) + 1e-6f);
    __syncthreads();

    size_t gbase = ((size_t)b * LL + l0) * DIMM;
    #pragma unroll
    for (int it = 0; it < 24; it++) {
        int idx = tid + it * 256;
        int t2 = idx / DIMM, d = idx - t2 * DIMM;
        float raw = tile[d][t2];
        xs[gbase + (size_t)t2 * DIMM + d] = raw;
        xnb[gbase + (size_t)t2 * DIMM + d] =
            __float2bfloat16_rn(raw * rinv[t2] * n1[d]);
    }
}

// ---------------------------------------------------------------------------
// Output transpose
// ---------------------------------------------------------------------------
__global__ void transpose_kernel(const float* __restrict__ in,
                                 float* __restrict__ out,
                                 int rows, int cols) {
    __shared__ float tile[32][33];
    int bx = blockIdx.x * 32;
    int by = blockIdx.y * 32;
    size_t plane = (size_t)rows * cols;
    const float* inb = in + (size_t)blockIdx.z * plane;
    float* outb      = out + (size_t)blockIdx.z * plane;
    int tx = threadIdx.x, ty = threadIdx.y;
    #pragma unroll
    for (int i = 0; i < 32; i += 8)
        tile[ty + i][tx] = inb[(size_t)(by + ty + i) * cols + bx + tx];
    __syncthreads();
    #pragma unroll
    for (int i = 0; i < 32; i += 8)
        outb[(size_t)(bx + ty + i) * rows + by + tx] = tile[tx][ty + i];
}

// ---------------------------------------------------------------------------
// rms2
// ---------------------------------------------------------------------------
__global__ void rms_kernel(const float* __restrict__ in,
                           const float* __restrict__ scale,
                           bf16* __restrict__ out) {
    int tok = blockIdx.x;
    int tid = threadIdx.x;
    const float* row = in + (size_t)tok * DIMM;
    float v0 = row[tid], v1 = row[tid + 128], v2 = row[tid + 256];
    float s = v0*v0 + v1*v1 + v2*v2;
    #pragma unroll
    for (int off = 16; off > 0; off >>= 1)
        s += __shfl_down_sync(0xffffffffu, s, off);
    __shared__ float red[4];
    if ((tid & 31) == 0) red[tid >> 5] = s;
    __syncthreads();
    if (tid == 0) {
        float t = red[0] + red[1] + red[2] + red[3];
        red[0] = rsqrtf(t * (1.0f / DIMM) + 1e-6f);
    }
    __syncthreads();
    float rinv = red[0];
    bf16* orow = out + (size_t)tok * DIMM;
    orow[tid]       = __float2bfloat16_rn(v0 * rinv * scale[tid]);
    orow[tid + 128] = __float2bfloat16_rn(v1 * rinv * scale[tid + 128]);
    orow[tid + 256] = __float2bfloat16_rn(v2 * rinv * scale[tid + 256]);
}

// ---------------------------------------------------------------------------
// QK rms-norm + RoPE on bf16 qkv, warp-per-token. fp32 math inside.
// ---------------------------------------------------------------------------
__global__ __launch_bounds__(128)
void qkrope_kernel(bf16* __restrict__ qkv,
                   const float* __restrict__ nq,
                   const float* __restrict__ nk,
                   const float* __restrict__ cosT,
                   const float* __restrict__ sinT) {
    int tid = threadIdx.x;
    int lane = tid & 31;
    int tok = blockIdx.x * 4 + (tid >> 5);
    size_t base = (size_t)tok * QKVN;
    bf16* qp = qkv + base;
    bf16* kp = qkv + base + DIMM;

    float q[12], k[12];
    float ssq = 0.f, ssk = 0.f;
    #pragma unroll
    for (int i = 0; i < 3; i++) {
        int e0 = i * 128 + lane * 4;
        uint2 qw = *(const uint2*)(qp + e0);
        uint2 kw = *(const uint2*)(kp + e0);
        float2 qa = unpackbf(qw.x), qb = unpackbf(qw.y);
        float2 ka = unpackbf(kw.x), kb = unpackbf(kw.y);
        q[i*4+0] = qa.x; q[i*4+1] = qa.y; q[i*4+2] = qb.x; q[i*4+3] = qb.y;
        k[i*4+0] = ka.x; k[i*4+1] = ka.y; k[i*4+2] = kb.x; k[i*4+3] = kb.y;
        ssq += qa.x*qa.x + qa.y*qa.y + qb.x*qb.x + qb.y*qb.y;
        ssk += ka.x*ka.x + ka.y*ka.y + kb.x*kb.x + kb.y*kb.y;
    }
    #pragma unroll
    for (int m = 16; m >= 1; m >>= 1) {
        ssq += __shfl_xor_sync(0xffffffffu, ssq, m);
        ssk += __shfl_xor_sync(0xffffffffu, ssk, m);
    }
    float rq = rsqrtf(ssq * (1.0f / DIMM) + 1e-6f);
    float rk = rsqrtf(ssk * (1.0f / DIMM) + 1e-6f);

    int l = tok & (LL - 1);
    int j2 = 2 * (lane & 7);
    float c0 = cosT[l * 16 + j2],     s0 = sinT[l * 16 + j2];
    float c1 = cosT[l * 16 + j2 + 1], s1 = sinT[l * 16 + j2 + 1];

    #pragma unroll
    for (int i = 0; i < 3; i++) {
        int e0 = i * 128 + lane * 4;
        float4 nqv = *(const float4*)(nq + e0);
        float4 nkv = *(const float4*)(nk + e0);
        float a0 = q[i*4+0] * rq * nqv.x, a1 = q[i*4+1] * rq * nqv.y;
        float a2 = q[i*4+2] * rq * nqv.z, a3 = q[i*4+3] * rq * nqv.w;
        uint2 qo;
        qo.x = packbf(a0 * c0 - a1 * s0, a0 * s0 + a1 * c0);
        qo.y = packbf(a2 * c1 - a3 * s1, a2 * s1 + a3 * c1);
        *(uint2*)(qp + e0) = qo;
        float b0 = k[i*4+0] * rk * nkv.x, b1 = k[i*4+1] * rk * nkv.y;
        float b2 = k[i*4+2] * rk * nkv.z, b3 = k[i*4+3] * rk * nkv.w;
        uint2 ko;
        ko.x = packbf(b0 * c0 - b1 * s0, b0 * s0 + b1 * c0);
        ko.y = packbf(b2 * c1 - b3 * s1, b2 * s1 + b3 * c1);
        *(uint2*)(kp + e0) = ko;
    }
}

// ---------------------------------------------------------------------------
// Tensor-core attention: warp-per-(group,head), bf16 mma, fp32 softmax.
// qkv is bf16 (staged directly). MODE 0 write / 1 += / 2 += & emit bf16.
// ---------------------------------------------------------------------------
template <int VAR>
__device__ __forceinline__ int tok_of(int g, int s) {
    if (VAR == 0) { int b = g >> 7, t = g & 127; return b * LL + t * FRR + s; }
    if (VAR == 1) { int b = g >> 6, fr = g & 63; return b * LL + s * FRR + fr; }
    int b = g >> 8, r = g & 255;
    int t1 = r >> 3, f1 = r & 7;
    int t2 = s >> 3, f2 = s & 7;
    return b * LL + (t1 * 4 + t2) * FRR + f1 * 8 + f2;
}

template <int VAR, int S, int MODE>
__global__ __launch_bounds__(128)
void attn_mma(const bf16* __restrict__ qkv,
              float* __restrict__ ysum, bf16* __restrict__ ysb) {
    extern __shared__ char asmem[];
    constexpr int QSTR = 40;
    constexpr int VSTR = S + 8;
    constexpr int QSZ  = S * QSTR;
    constexpr int VTSZ = 32 * VSTR;
    constexpr int JOB  = 2 * QSZ + VTSZ;

    int tid = threadIdx.x, wid = tid >> 5, lane = tid & 31;
    int g = blockIdx.x * 4 + wid;
    int h = blockIdx.y;

    bf16* Qs = (bf16*)asmem + (size_t)wid * JOB;
    bf16* Ks = Qs + QSZ;
    bf16* Vt = Ks + QSZ;

    for (int j = 0; j < S; j++) {
        size_t base = (size_t)tok_of<VAR>(g, j) * QKVN + h * HDIM + lane;
        bf16 qv = qkv[base];
        bf16 kv = qkv[base + 384];
        bf16 vv = qkv[base + 768];
        Qs[j * QSTR + lane] = qv;
        Ks[j * QSTR + lane] = kv;
        Vt[lane * VSTR + j] = vv;
    }
    __syncwarp();

    uint32_t Qu = (uint32_t)__cvta_generic_to_shared(Qs);
    uint32_t Ku = (uint32_t)__cvta_generic_to_shared(Ks);
    uint32_t Vu = (uint32_t)__cvta_generic_to_shared(Vt);

    int mrow = lane & 7, sel = lane >> 3;
    int a_row = (sel & 1) * 8 + mrow, a_k = (sel >> 1) * 8;
    int b_row = (sel >> 1) * 8 + mrow, b_k = (sel & 1) * 8;
    int gid = lane >> 2, tid4 = lane & 3;
    const float rscale = 0.17677669529663687f;

    for (int mt = 0; mt < S / 16; mt++) {
        unsigned aq[2][4];
        #pragma unroll
        for (int ks = 0; ks < 2; ks++) {
            uint32_t addr = Qu +
                (uint32_t)((mt * 16 + a_row) * QSTR + ks * 16 + a_k) * 2;
            ldsm4(aq[ks][0], aq[ks][1], aq[ks][2], aq[ks][3], addr);
        }

        float cy[4][4];
        #pragma unroll
        for (int nt = 0; nt < 4; nt++)
            #pragma unroll
            for (int r = 0; r < 4; r++) cy[nt][r] = 0.f;
        float ls0 = 0.f, ls1 = 0.f;

        for (int jt = 0; jt < S / 16; jt++) {
            unsigned bk[2][2][2];
            #pragma unroll
            for (int ks = 0; ks < 2; ks++) {
                uint32_t addr = Ku +
                    (uint32_t)((jt * 16 + b_row) * QSTR + ks * 16 + b_k) * 2;
                ldsm4(bk[ks][0][0], bk[ks][0][1], bk[ks][1][0], bk[ks][1][1], addr);
            }
            float sc[2][4];
            #pragma unroll
            for (int nt = 0; nt < 2; nt++)
                #pragma unroll
                for (int r = 0; r < 4; r++) sc[nt][r] = 0.f;
            #pragma unroll
            for (int ks = 0; ks < 2; ks++)
                #pragma unroll
                for (int nt = 0; nt < 2; nt++)
                    mma_bf16(sc[nt], aq[ks], bk[ks][nt]);

            float p00 = __expf(sc[0][0] * rscale), p01 = __expf(sc[0][1] * rscale);
            float p02 = __expf(sc[0][2] * rscale), p03 = __expf(sc[0][3] * rscale);
            float p10 = __expf(sc[1][0] * rscale), p11 = __expf(sc[1][1] * rscale);
            float p12 = __expf(sc[1][2] * rscale), p13 = __expf(sc[1][3] * rscale);
            ls0 += p00 + p01 + p10 + p11;
            ls1 += p02 + p03 + p12 + p13;
            unsigned pa[4];
            pa[0] = packbf(p00, p01);
            pa[1] = packbf(p02, p03);
            pa[2] = packbf(p10, p11);
            pa[3] = packbf(p12, p13);

            unsigned bv[4][2];
            #pragma unroll
            for (int np = 0; np < 2; np++) {
                uint32_t addr = Vu +
                    (uint32_t)((np * 16 + b_row) * VSTR + jt * 16 + b_k) * 2;
                ldsm4(bv[2*np][0], bv[2*np][1], bv[2*np+1][0], bv[2*np+1][1], addr);
            }
            #pragma unroll
            for (int nt = 0; nt < 4; nt++)
                mma_bf16(cy[nt], pa, bv[nt]);
        }

        ls0 += __shfl_xor_sync(0xffffffffu, ls0, 1);
        ls0 += __shfl_xor_sync(0xffffffffu, ls0, 2);
        ls1 += __shfl_xor_sync(0xffffffffu, ls1, 1);
        ls1 += __shfl_xor_sync(0xffffffffu, ls1, 2);
        float inv0 = 1.f / ls0, inv1 = 1.f / ls1;

        int r0 = mt * 16 + gid, r1 = r0 + 8;
        size_t o0 = (size_t)tok_of<VAR>(g, r0) * DIMM + h * HDIM;
        size_t o1 = (size_t)tok_of<VAR>(g, r1) * DIMM + h * HDIM;
        #pragma unroll
        for (int nt = 0; nt < 4; nt++) {
            int cc = nt * 8 + 2 * tid4;
            float v00 = cy[nt][0] * inv0, v01 = cy[nt][1] * inv0;
            float v10 = cy[nt][2] * inv1, v11 = cy[nt][3] * inv1;
            float* p0 = ysum + o0 + cc;
            float* p1 = ysum + o1 + cc;
            if (MODE == 0) {
                *(float2*)p0 = make_float2(v00, v01);
                *(float2*)p1 = make_float2(v10, v11);
            } else if (MODE == 1) {
                float2 a0 = *(float2*)p0, a1 = *(float2*)p1;
                *(float2*)p0 = make_float2(a0.x + v00, a0.y + v01);
                *(float2*)p1 = make_float2(a1.x + v10, a1.y + v11);
            } else {
                float2 a0 = *(float2*)p0, a1 = *(float2*)p1;
                float t00 = a0.x + v00, t01 = a0.y + v01;
                float t10 = a1.x + v10, t11 = a1.y + v11;
                *(float2*)p0 = make_float2(t00, t01);
                *(float2*)p1 = make_float2(t10, t11);
                *(bf162*)(ysb + o0 + cc) = __floats2bfloat162_rn(t00, t01);
                *(bf162*)(ysb + o1 + cc) = __floats2bfloat162_rn(t10, t11);
            }
        }
    }
}

#define ATTN_SMEM(S) (4 * (2 * (S) * 40 + 32 * ((S) + 8)) * 2)

// ---------------------------------------------------------------------------
// bf16 mma.sync GEMM (2-stage cp.async, ldmatrix, GBK=64)
// EPI 0: f32 store; 1: bf16 gelu store; 2: f32 +=; 3: bf16 store.
// ---------------------------------------------------------------------------
#define GBM 128
#define GBN 128
#define GBK 64
#define KSTR 72
#define ATILE (2 * GBM * KSTR)
#define GEMM_SMEM_BYTES (2 * ATILE * 2)

template <int EPI>
__global__ __launch_bounds__(256)
void mma_gemm(const bf16* __restrict__ A, const bf16* __restrict__ Wt,
              const float* __restrict__ bias, void* __restrict__ Cv,
              int M, int N, int K) {
    extern __shared__ char dynsmem[];
    bf16* As = (bf16*)dynsmem;
    bf16* Bs = (bf16*)(dynsmem + ATILE * 2);

    int tid  = threadIdx.x;
    int n0   = blockIdx.x * GBN, m0 = blockIdx.y * GBM;
    int warp = tid >> 5, lane = tid & 31;
    int wm   = (warp & 3) * 32;
    int wn   = (warp >> 2) * 64;

    const bf16* Abase = A  + (size_t)m0 * K;
    const bf16* Bbase = Wt + (size_t)n0 * K;

    int mrow = lane & 7;
    int sel  = lane >> 3;
    int a_row_add = (sel & 1) * 8 + mrow;
    int a_k_add   = (sel >> 1) * 8;
    int b_row_add = (sel >> 1) * 8 + mrow;
    int b_k_add   = (sel & 1) * 8;

    uint32_t As_u = (uint32_t)__cvta_generic_to_shared(As);
    uint32_t Bs_u = (uint32_t)__cvta_generic_to_shared(Bs);

    float c[2][8][4];
    #pragma unroll
    for (int mt = 0; mt < 2; mt++)
        #pragma unroll
        for (int nt = 0; nt < 8; nt++)
            #pragma unroll
            for (int r = 0; r < 4; r++) c[mt][nt][r] = 0.f;

    auto load_tiles = [&](int buf, int k0) {
        bf16* Ad = As + buf * GBM * KSTR;
        bf16* Bd = Bs + buf * GBN * KSTR;
        #pragma unroll
        for (int i = 0; i < 4; i++) {
            int ch = tid + i * 256;
            int r = ch >> 3, cc = ch & 7;
            cp16((uint32_t)__cvta_generic_to_shared(Ad + r * KSTR + cc * 8),
                 Abase + (size_t)r * K + k0 + cc * 8);
            cp16((uint32_t)__cvta_generic_to_shared(Bd + r * KSTR + cc * 8),
                 Bbase + (size_t)r * K + k0 + cc * 8);
        }
    };

    int kTiles = K / GBK;
    load_tiles(0, 0);
    CP_COMMIT();

    for (int kt = 0; kt < kTiles; kt++) {
        int buf = kt & 1;
        if (kt + 1 < kTiles) {
            load_tiles(buf ^ 1, (kt + 1) * GBK);
            CP_COMMIT();
            CP_WAIT(1);
        } else {
            CP_WAIT(0);
        }
        __syncthreads();

        uint32_t Abuf = As_u + (uint32_t)(buf * GBM * KSTR) * 2;
        uint32_t Bbuf = Bs_u + (uint32_t)(buf * GBN * KSTR) * 2;

        #pragma unroll
        for (int ks = 0; ks < GBK; ks += 16) {
            unsigned af[2][4], bfr[8][2];
            #pragma unroll
            for (int mt = 0; mt < 2; mt++) {
                uint32_t addr = Abuf +
                    (uint32_t)((wm + mt * 16 + a_row_add) * KSTR + ks + a_k_add) * 2;
                ldsm4(af[mt][0], af[mt][1], af[mt][2], af[mt][3], addr);
            }
            #pragma unroll
            for (int np = 0; np < 4; np++) {
                uint32_t addr = Bbuf +
                    (uint32_t)((wn + np * 16 + b_row_add) * KSTR + ks + b_k_add) * 2;
                ldsm4(bfr[2*np][0], bfr[2*np][1], bfr[2*np+1][0], bfr[2*np+1][1], addr);
            }
            #pragma unroll
            for (int mt = 0; mt < 2; mt++)
                #pragma unroll
                for (int nt = 0; nt < 8; nt++)
                    mma_bf16(c[mt][nt], af[mt], bfr[nt]);
        }
        __syncthreads();
    }

    int gid  = lane >> 2, tid4 = lane & 3;
    #pragma unroll
    for (int mt = 0; mt < 2; mt++) {
        int r0 = m0 + wm + mt * 16 + gid;
        int r1 = r0 + 8;
        #pragma unroll
        for (int nt = 0; nt < 8; nt++) {
            int cc = n0 + wn + nt * 8 + 2 * tid4;
            float b0 = bias[cc], b1 = bias[cc + 1];
            float v00 = c[mt][nt][0] + b0, v01 = c[mt][nt][1] + b1;
            float v10 = c[mt][nt][2] + b0, v11 = c[mt][nt][3] + b1;
            if (EPI == 0) {
                float* C = (float*)Cv;
                *(float2*)(C + (size_t)r0 * N + cc) = make_float2(v00, v01);
                *(float2*)(C + (size_t)r1 * N + cc) = make_float2(v10, v11);
            } else if (EPI == 1) {
                bf16* C = (bf16*)Cv;
                *(bf162*)(C + (size_t)r0 * N + cc) =
                    __floats2bfloat162_rn(gelu_tanh(v00), gelu_tanh(v01));
                *(bf162*)(C + (size_t)r1 * N + cc) =
                    __floats2bfloat162_rn(gelu_tanh(v10), gelu_tanh(v11));
            } else if (EPI == 2) {
                float* C = (float*)Cv;
                float* p0 = C + (size_t)r0 * N + cc;
                float* p1 = C + (size_t)r1 * N + cc;
                float2 o0 = *(float2*)p0, o1 = *(float2*)p1;
                *(float2*)p0 = make_float2(o0.x + v00, o0.y + v01);
                *(float2*)p1 = make_float2(o1.x + v10, o1.y + v11);
            } else {
                bf16* C = (bf16*)Cv;
                *(bf162*)(C + (size_t)r0 * N + cc) = __floats2bfloat162_rn(v00, v01);
                *(bf162*)(C + (size_t)r1 * N + cc) = __floats2bfloat162_rn(v10, v11);
            }
        }
    }
}

// ---------------------------------------------------------------------------
// kernel_launch
// ---------------------------------------------------------------------------
extern "C" void kernel_launch(void* const* d_in, const int* in_sizes, int n_in,
                              void* d_out, int out_size) {
    const float* x      = (const float*)d_in[0];
    const float* cosT   = (const float*)d_in[1];
    const float* sinT   = (const float*)d_in[2];
    const float* qkv_w  = (const float*)d_in[3];
    const float* qkv_b  = (const float*)d_in[4];
    const float* nq_s   = (const float*)d_in[5];
    const float* nk_s   = (const float*)d_in[6];
    const float* proj_w = (const float*)d_in[7];
    const float* proj_b = (const float*)d_in[8];
    const float* n1_s   = (const float*)d_in[9];
    const float* n2_s   = (const float*)d_in[10];
    const float* w1     = (const float*)d_in[11];
    const float* b1     = (const float*)d_in[12];
    const float* w2     = (const float*)d_in[13];
    const float* b2     = (const float*)d_in[14];
    float* out = (float*)d_out;

    float *xs, *ysum;
    bf16 *xnb, *qkvb, *ysb, *hb, *h1b, *wq, *wp, *ww1, *ww2;
    cudaGetSymbolAddress((void**)&xs,   g_xs);
    cudaGetSymbolAddress((void**)&xnb,  g_xnb);
    cudaGetSymbolAddress((void**)&qkvb, g_qkvb);
    cudaGetSymbolAddress((void**)&ysum, g_ysum);
    cudaGetSymbolAddress((void**)&ysb,  g_ysb);
    cudaGetSymbolAddress((void**)&hb,   g_hb);
    cudaGetSymbolAddress((void**)&h1b,  g_h1b);
    cudaGetSymbolAddress((void**)&wq,   g_wqkv);
    cudaGetSymbolAddress((void**)&wp,   g_wproj);
    cudaGetSymbolAddress((void**)&ww1,  g_w1);
    cudaGetSymbolAddress((void**)&ww2,  g_w2);

    cudaFuncSetAttribute(mma_gemm<1>, cudaFuncAttributeMaxDynamicSharedMemorySize, GEMM_SMEM_BYTES);
    cudaFuncSetAttribute(mma_gemm<2>, cudaFuncAttributeMaxDynamicSharedMemorySize, GEMM_SMEM_BYTES);
    cudaFuncSetAttribute(mma_gemm<3>, cudaFuncAttributeMaxDynamicSharedMemorySize, GEMM_SMEM_BYTES);
    cudaFuncSetAttribute(attn_mma<0, 64, 0>, cudaFuncAttributeMaxDynamicSharedMemorySize, ATTN_SMEM(64));
    cudaFuncSetAttribute(attn_mma<1, 128, 1>, cudaFuncAttributeMaxDynamicSharedMemorySize, ATTN_SMEM(128));
    cudaFuncSetAttribute(attn_mma<2, 32, 2>, cudaFuncAttributeMaxDynamicSharedMemorySize, ATTN_SMEM(32));

    dim3 tb(32, 8);

    // weight prep
    wprep_kernel<<<dim3(QKVN/32, DIMM/32), tb>>>(qkv_w, wq, DIMM, QKVN);
    wprep_kernel<<<dim3(DIMM/32, DIMM/32), tb>>>(proj_w, wp, DIMM, DIMM);
    wprep_kernel<<<dim3(FFN/32,  DIMM/32), tb>>>(w1, ww1, DIMM, FFN);
    wprep_kernel<<<dim3(DIMM/32, FFN/32),  tb>>>(w2, ww2, FFN, DIMM);

    // fused transpose + rms1
    fuse_in_kernel<<<dim3(LL/16, BB), 256>>>(x, n1_s, xs, xnb);

    // qkvb = bf16(xnb @ wq^T + qkv_b)
    mma_gemm<3><<<dim3(QKVN/GBN, NTOK/GBM), 256, GEMM_SMEM_BYTES>>>(
        xnb, wq, qkv_b, qkvb, NTOK, QKVN, DIMM);

    // q/k rmsnorm + rope (bf16 in/out)
    qkrope_kernel<<<NTOK/4, 128>>>(qkvb, nq_s, nk_s, cosT, sinT);

    // three attentions (tensor-core)
    attn_mma<0, 64,  0><<<dim3(BB * TT / 4,  NHEAD), 128, ATTN_SMEM(64)>>>(qkvb, ysum, ysb);
    attn_mma<1, 128, 1><<<dim3(BB * FRR / 4, NHEAD), 128, ATTN_SMEM(128)>>>(qkvb, ysum, ysb);
    attn_mma<2, 32,  2><<<dim3(BB * 256 / 4, NHEAD), 128, ATTN_SMEM(32)>>>(qkvb, ysum, ysb);

    // xs += ysb @ wp^T + proj_b
    mma_gemm<2><<<dim3(DIMM/GBN, NTOK/GBM), 256, GEMM_SMEM_BYTES>>>(
        ysb, wp, proj_b, xs, NTOK, DIMM, DIMM);

    // hb = bf16(rms(xs, n2))
    rms_kernel<<<NTOK, 128>>>(xs, n2_s, hb);

    // h1b = bf16(gelu(hb @ ww1^T + b1))
    mma_gemm<1><<<dim3(FFN/GBN, NTOK/GBM), 256, GEMM_SMEM_BYTES>>>(
        hb, ww1, b1, h1b, NTOK, FFN, DIMM);

    // xs += h1b @ ww2^T + b2
    mma_gemm<2><<<dim3(DIMM/GBN, NTOK/GBM), 256, GEMM_SMEM_BYTES>>>(
        h1b, ww2, b2, xs, NTOK, DIMM, FFN);

    // xs -> out
    transpose_kernel<<<dim3(DIMM/32, LL/32, BB), tb>>>(xs, out, LL, DIMM);
}

// round 15
// speedup vs baseline: 1.7338x; 1.0001x over previous
#include <cuda_runtime.h>
#include <cuda_bf16.h>
#include <math.h>
#include <stdint.h>

#define BB    4
#define TT    128
#define FRR   64
#define LL    8192
#define DIMM  384
#define NHEAD 12
#define HDIM  32
#define NTOK  (BB*LL)
#define QKVN  (3*DIMM)
#define FFN   (4*DIMM)

typedef __nv_bfloat16  bf16;
typedef __nv_bfloat162 bf162;

// ---------------------------------------------------------------------------
// Scratch
// ---------------------------------------------------------------------------
__device__ float g_xs  [(size_t)NTOK * DIMM];
__device__ bf16  g_xnb [(size_t)NTOK * DIMM];
__device__ bf16  g_qkvb[(size_t)NTOK * QKVN];
__device__ float g_ysum[(size_t)NTOK * DIMM];
__device__ bf16  g_ysb [(size_t)NTOK * DIMM];
__device__ bf16  g_hb  [(size_t)NTOK * DIMM];
__device__ bf16  g_h1b [(size_t)NTOK * FFN];
__device__ bf16  g_wqkv [QKVN * DIMM];
__device__ bf16  g_wproj[DIMM * DIMM];
__device__ bf16  g_w1   [FFN * DIMM];
__device__ bf16  g_w2   [DIMM * FFN];

// ---------------------------------------------------------------------------
// common PTX helpers
// ---------------------------------------------------------------------------
__device__ __forceinline__ void cp16(uint32_t smem, const void* gmem) {
    asm volatile("cp.async.cg.shared.global [%0], [%1], 16;\n" :: "r"(smem), "l"(gmem));
}
#define CP_COMMIT() asm volatile("cp.async.commit_group;\n" ::: "memory")
#define CP_WAIT(n)  asm volatile("cp.async.wait_group %0;\n" :: "n"(n) : "memory")

__device__ __forceinline__ void ldsm4(unsigned& r0, unsigned& r1,
                                      unsigned& r2, unsigned& r3, unsigned addr) {
    asm volatile("ldmatrix.sync.aligned.m8n8.x4.shared.b16 {%0,%1,%2,%3}, [%4];\n"
                 : "=r"(r0), "=r"(r1), "=r"(r2), "=r"(r3) : "r"(addr));
}

__device__ __forceinline__ void mma_bf16(float* c, const unsigned* a, const unsigned* b) {
    asm volatile(
        "mma.sync.aligned.m16n8k16.row.col.f32.bf16.bf16.f32 "
        "{%0,%1,%2,%3}, {%4,%5,%6,%7}, {%8,%9}, {%0,%1,%2,%3};\n"
        : "+f"(c[0]), "+f"(c[1]), "+f"(c[2]), "+f"(c[3])
        : "r"(a[0]), "r"(a[1]), "r"(a[2]), "r"(a[3]), "r"(b[0]), "r"(b[1]));
}

__device__ __forceinline__ unsigned packbf(float lo, float hi) {
    bf162 v = __floats2bfloat162_rn(lo, hi);
    unsigned u;
    memcpy(&u, &v, 4);
    return u;
}

__device__ __forceinline__ float2 unpackbf(unsigned u) {
    bf162 v;
    memcpy(&v, &u, 4);
    return __bfloat1622float2(v);
}

__device__ __forceinline__ float gelu_tanh(float x) {
    float c = 0.7978845608028654f;
    float t = tanhf(c * (x + 0.044715f * x * x * x));
    return 0.5f * x * (1.0f + t);
}

// ---------------------------------------------------------------------------
// Weight prep: w [K][N] f32 -> wt [N][K] bf16
// ---------------------------------------------------------------------------
__global__ void wprep_kernel(const float* __restrict__ w,
                             bf16* __restrict__ wt, int K, int N) {
    __shared__ float tile[32][33];
    int n0 = blockIdx.x * 32, k0 = blockIdx.y * 32;
    int tx = threadIdx.x, ty = threadIdx.y;
    #pragma unroll
    for (int i = 0; i < 32; i += 8)
        tile[ty + i][tx] = w[(size_t)(k0 + ty + i) * N + n0 + tx];
    __syncthreads();
    #pragma unroll
    for (int i = 0; i < 32; i += 8)
        wt[(size_t)(n0 + ty + i) * K + k0 + tx] =
            __float2bfloat16_rn(tile[tx][ty + i]);
}

// ---------------------------------------------------------------------------
// Fused input transpose + rms1
// ---------------------------------------------------------------------------
__global__ __launch_bounds__(256)
void fuse_in_kernel(const float* __restrict__ x,
                    const float* __restrict__ n1,
                    float* __restrict__ xs, bf16* __restrict__ xnb) {
    __shared__ float tile[DIMM][17];
    __shared__ float rinv[16];
    int tid = threadIdx.x;
    int l0 = blockIdx.x * 16;
    int b  = blockIdx.y;
    const float* xb = x + (size_t)b * DIMM * LL + l0;

    #pragma unroll
    for (int it = 0; it < 24; it++) {
        int idx = tid + it * 256;
        int d = idx >> 4, c = idx & 15;
        tile[d][c] = xb[(size_t)d * LL + c];
    }
    __syncthreads();

    int tok = tid >> 4, j = tid & 15;
    float s = 0.f;
    #pragma unroll
    for (int k = 0; k < 24; k++) {
        float v = tile[j + 16 * k][tok];
        s += v * v;
    }
    #pragma unroll
    for (int m = 8; m >= 1; m >>= 1)
        s += __shfl_xor_sync(0xffffffffu, s, m);
    if (j == 0) rinv[tok] = rsqrtf(s * (1.0f / DIMM) + 1e-6f);
    __syncthreads();

    size_t gbase = ((size_t)b * LL + l0) * DIMM;
    #pragma unroll
    for (int it = 0; it < 24; it++) {
        int idx = tid + it * 256;
        int t2 = idx / DIMM, d = idx - t2 * DIMM;
        float raw = tile[d][t2];
        xs[gbase + (size_t)t2 * DIMM + d] = raw;
        xnb[gbase + (size_t)t2 * DIMM + d] =
            __float2bfloat16_rn(raw * rinv[t2] * n1[d]);
    }
}

// ---------------------------------------------------------------------------
// rms2
// ---------------------------------------------------------------------------
__global__ void rms_kernel(const float* __restrict__ in,
                           const float* __restrict__ scale,
                           bf16* __restrict__ out) {
    int tok = blockIdx.x;
    int tid = threadIdx.x;
    const float* row = in + (size_t)tok * DIMM;
    float v0 = row[tid], v1 = row[tid + 128], v2 = row[tid + 256];
    float s = v0*v0 + v1*v1 + v2*v2;
    #pragma unroll
    for (int off = 16; off > 0; off >>= 1)
        s += __shfl_down_sync(0xffffffffu, s, off);
    __shared__ float red[4];
    if ((tid & 31) == 0) red[tid >> 5] = s;
    __syncthreads();
    if (tid == 0) {
        float t = red[0] + red[1] + red[2] + red[3];
        red[0] = rsqrtf(t * (1.0f / DIMM) + 1e-6f);
    }
    __syncthreads();
    float rinv = red[0];
    bf16* orow = out + (size_t)tok * DIMM;
    orow[tid]       = __float2bfloat16_rn(v0 * rinv * scale[tid]);
    orow[tid + 128] = __float2bfloat16_rn(v1 * rinv * scale[tid + 128]);
    orow[tid + 256] = __float2bfloat16_rn(v2 * rinv * scale[tid + 256]);
}

// ---------------------------------------------------------------------------
// QK rms-norm + RoPE on bf16 qkv, warp-per-token. fp32 math inside.
// ---------------------------------------------------------------------------
__global__ __launch_bounds__(128)
void qkrope_kernel(bf16* __restrict__ qkv,
                   const float* __restrict__ nq,
                   const float* __restrict__ nk,
                   const float* __restrict__ cosT,
                   const float* __restrict__ sinT) {
    int tid = threadIdx.x;
    int lane = tid & 31;
    int tok = blockIdx.x * 4 + (tid >> 5);
    size_t base = (size_t)tok * QKVN;
    bf16* qp = qkv + base;
    bf16* kp = qkv + base + DIMM;

    float q[12], k[12];
    float ssq = 0.f, ssk = 0.f;
    #pragma unroll
    for (int i = 0; i < 3; i++) {
        int e0 = i * 128 + lane * 4;
        uint2 qw = *(const uint2*)(qp + e0);
        uint2 kw = *(const uint2*)(kp + e0);
        float2 qa = unpackbf(qw.x), qb = unpackbf(qw.y);
        float2 ka = unpackbf(kw.x), kb = unpackbf(kw.y);
        q[i*4+0] = qa.x; q[i*4+1] = qa.y; q[i*4+2] = qb.x; q[i*4+3] = qb.y;
        k[i*4+0] = ka.x; k[i*4+1] = ka.y; k[i*4+2] = kb.x; k[i*4+3] = kb.y;
        ssq += qa.x*qa.x + qa.y*qa.y + qb.x*qb.x + qb.y*qb.y;
        ssk += ka.x*ka.x + ka.y*ka.y + kb.x*kb.x + kb.y*kb.y;
    }
    #pragma unroll
    for (int m = 16; m >= 1; m >>= 1) {
        ssq += __shfl_xor_sync(0xffffffffu, ssq, m);
        ssk += __shfl_xor_sync(0xffffffffu, ssk, m);
    }
    float rq = rsqrtf(ssq * (1.0f / DIMM) + 1e-6f);
    float rk = rsqrtf(ssk * (1.0f / DIMM) + 1e-6f);

    int l = tok & (LL - 1);
    int j2 = 2 * (lane & 7);
    float c0 = cosT[l * 16 + j2],     s0 = sinT[l * 16 + j2];
    float c1 = cosT[l * 16 + j2 + 1], s1 = sinT[l * 16 + j2 + 1];

    #pragma unroll
    for (int i = 0; i < 3; i++) {
        int e0 = i * 128 + lane * 4;
        float4 nqv = *(const float4*)(nq + e0);
        float4 nkv = *(const float4*)(nk + e0);
        float a0 = q[i*4+0] * rq * nqv.x, a1 = q[i*4+1] * rq * nqv.y;
        float a2 = q[i*4+2] * rq * nqv.z, a3 = q[i*4+3] * rq * nqv.w;
        uint2 qo;
        qo.x = packbf(a0 * c0 - a1 * s0, a0 * s0 + a1 * c0);
        qo.y = packbf(a2 * c1 - a3 * s1, a2 * s1 + a3 * c1);
        *(uint2*)(qp + e0) = qo;
        float b0 = k[i*4+0] * rk * nkv.x, b1 = k[i*4+1] * rk * nkv.y;
        float b2 = k[i*4+2] * rk * nkv.z, b3 = k[i*4+3] * rk * nkv.w;
        uint2 ko;
        ko.x = packbf(b0 * c0 - b1 * s0, b0 * s0 + b1 * c0);
        ko.y = packbf(b2 * c1 - b3 * s1, b2 * s1 + b3 * c1);
        *(uint2*)(kp + e0) = ko;
    }
}

// ---------------------------------------------------------------------------
// Tensor-core attention (unchanged from R14)
// ---------------------------------------------------------------------------
template <int VAR>
__device__ __forceinline__ int tok_of(int g, int s) {
    if (VAR == 0) { int b = g >> 7, t = g & 127; return b * LL + t * FRR + s; }
    if (VAR == 1) { int b = g >> 6, fr = g & 63; return b * LL + s * FRR + fr; }
    int b = g >> 8, r = g & 255;
    int t1 = r >> 3, f1 = r & 7;
    int t2 = s >> 3, f2 = s & 7;
    return b * LL + (t1 * 4 + t2) * FRR + f1 * 8 + f2;
}

template <int VAR, int S, int MODE>
__global__ __launch_bounds__(128)
void attn_mma(const bf16* __restrict__ qkv,
              float* __restrict__ ysum, bf16* __restrict__ ysb) {
    extern __shared__ char asmem[];
    constexpr int QSTR = 40;
    constexpr int VSTR = S + 8;
    constexpr int QSZ  = S * QSTR;
    constexpr int VTSZ = 32 * VSTR;
    constexpr int JOB  = 2 * QSZ + VTSZ;

    int tid = threadIdx.x, wid = tid >> 5, lane = tid & 31;
    int g = blockIdx.x * 4 + wid;
    int h = blockIdx.y;

    bf16* Qs = (bf16*)asmem + (size_t)wid * JOB;
    bf16* Ks = Qs + QSZ;
    bf16* Vt = Ks + QSZ;

    for (int j = 0; j < S; j++) {
        size_t base = (size_t)tok_of<VAR>(g, j) * QKVN + h * HDIM + lane;
        bf16 qv = qkv[base];
        bf16 kv = qkv[base + 384];
        bf16 vv = qkv[base + 768];
        Qs[j * QSTR + lane] = qv;
        Ks[j * QSTR + lane] = kv;
        Vt[lane * VSTR + j] = vv;
    }
    __syncwarp();

    uint32_t Qu = (uint32_t)__cvta_generic_to_shared(Qs);
    uint32_t Ku = (uint32_t)__cvta_generic_to_shared(Ks);
    uint32_t Vu = (uint32_t)__cvta_generic_to_shared(Vt);

    int mrow = lane & 7, sel = lane >> 3;
    int a_row = (sel & 1) * 8 + mrow, a_k = (sel >> 1) * 8;
    int b_row = (sel >> 1) * 8 + mrow, b_k = (sel & 1) * 8;
    int gid = lane >> 2, tid4 = lane & 3;
    const float rscale = 0.17677669529663687f;

    for (int mt = 0; mt < S / 16; mt++) {
        unsigned aq[2][4];
        #pragma unroll
        for (int ks = 0; ks < 2; ks++) {
            uint32_t addr = Qu +
                (uint32_t)((mt * 16 + a_row) * QSTR + ks * 16 + a_k) * 2;
            ldsm4(aq[ks][0], aq[ks][1], aq[ks][2], aq[ks][3], addr);
        }

        float cy[4][4];
        #pragma unroll
        for (int nt = 0; nt < 4; nt++)
            #pragma unroll
            for (int r = 0; r < 4; r++) cy[nt][r] = 0.f;
        float ls0 = 0.f, ls1 = 0.f;

        for (int jt = 0; jt < S / 16; jt++) {
            unsigned bk[2][2][2];
            #pragma unroll
            for (int ks = 0; ks < 2; ks++) {
                uint32_t addr = Ku +
                    (uint32_t)((jt * 16 + b_row) * QSTR + ks * 16 + b_k) * 2;
                ldsm4(bk[ks][0][0], bk[ks][0][1], bk[ks][1][0], bk[ks][1][1], addr);
            }
            float sc[2][4];
            #pragma unroll
            for (int nt = 0; nt < 2; nt++)
                #pragma unroll
                for (int r = 0; r < 4; r++) sc[nt][r] = 0.f;
            #pragma unroll
            for (int ks = 0; ks < 2; ks++)
                #pragma unroll
                for (int nt = 0; nt < 2; nt++)
                    mma_bf16(sc[nt], aq[ks], bk[ks][nt]);

            float p00 = __expf(sc[0][0] * rscale), p01 = __expf(sc[0][1] * rscale);
            float p02 = __expf(sc[0][2] * rscale), p03 = __expf(sc[0][3] * rscale);
            float p10 = __expf(sc[1][0] * rscale), p11 = __expf(sc[1][1] * rscale);
            float p12 = __expf(sc[1][2] * rscale), p13 = __expf(sc[1][3] * rscale);
            ls0 += p00 + p01 + p10 + p11;
            ls1 += p02 + p03 + p12 + p13;
            unsigned pa[4];
            pa[0] = packbf(p00, p01);
            pa[1] = packbf(p02, p03);
            pa[2] = packbf(p10, p11);
            pa[3] = packbf(p12, p13);

            unsigned bv[4][2];
            #pragma unroll
            for (int np = 0; np < 2; np++) {
                uint32_t addr = Vu +
                    (uint32_t)((np * 16 + b_row) * VSTR + jt * 16 + b_k) * 2;
                ldsm4(bv[2*np][0], bv[2*np][1], bv[2*np+1][0], bv[2*np+1][1], addr);
            }
            #pragma unroll
            for (int nt = 0; nt < 4; nt++)
                mma_bf16(cy[nt], pa, bv[nt]);
        }

        ls0 += __shfl_xor_sync(0xffffffffu, ls0, 1);
        ls0 += __shfl_xor_sync(0xffffffffu, ls0, 2);
        ls1 += __shfl_xor_sync(0xffffffffu, ls1, 1);
        ls1 += __shfl_xor_sync(0xffffffffu, ls1, 2);
        float inv0 = 1.f / ls0, inv1 = 1.f / ls1;

        int r0 = mt * 16 + gid, r1 = r0 + 8;
        size_t o0 = (size_t)tok_of<VAR>(g, r0) * DIMM + h * HDIM;
        size_t o1 = (size_t)tok_of<VAR>(g, r1) * DIMM + h * HDIM;
        #pragma unroll
        for (int nt = 0; nt < 4; nt++) {
            int cc = nt * 8 + 2 * tid4;
            float v00 = cy[nt][0] * inv0, v01 = cy[nt][1] * inv0;
            float v10 = cy[nt][2] * inv1, v11 = cy[nt][3] * inv1;
            float* p0 = ysum + o0 + cc;
            float* p1 = ysum + o1 + cc;
            if (MODE == 0) {
                *(float2*)p0 = make_float2(v00, v01);
                *(float2*)p1 = make_float2(v10, v11);
            } else if (MODE == 1) {
                float2 a0 = *(float2*)p0, a1 = *(float2*)p1;
                *(float2*)p0 = make_float2(a0.x + v00, a0.y + v01);
                *(float2*)p1 = make_float2(a1.x + v10, a1.y + v11);
            } else {
                float2 a0 = *(float2*)p0, a1 = *(float2*)p1;
                float t00 = a0.x + v00, t01 = a0.y + v01;
                float t10 = a1.x + v10, t11 = a1.y + v11;
                *(float2*)p0 = make_float2(t00, t01);
                *(float2*)p1 = make_float2(t10, t11);
                *(bf162*)(ysb + o0 + cc) = __floats2bfloat162_rn(t00, t01);
                *(bf162*)(ysb + o1 + cc) = __floats2bfloat162_rn(t10, t11);
            }
        }
    }
}

#define ATTN_SMEM(S) (4 * (2 * (S) * 40 + 32 * ((S) + 8)) * 2)

// ---------------------------------------------------------------------------
// bf16 mma.sync GEMM (2-stage cp.async, ldmatrix, GBK=64)
// EPI 0: f32 store; 1: bf16 gelu store; 2: f32 +=; 3: bf16 store;
// EPI 4: read Res (f32 residual), add, write TRANSPOSED to out (B,DIM,L).
// ---------------------------------------------------------------------------
#define GBM 128
#define GBN 128
#define GBK 64
#define KSTR 72
#define ATILE (2 * GBM * KSTR)
#define GEMM_SMEM_BYTES (2 * ATILE * 2)
// EPI4 reuses dynsmem as f32 tile [128][129] = 66048 B (< GEMM_SMEM_BYTES)
#define TSTR 129

template <int EPI>
__global__ __launch_bounds__(256)
void mma_gemm(const bf16* __restrict__ A, const bf16* __restrict__ Wt,
              const float* __restrict__ bias, void* __restrict__ Cv,
              const float* __restrict__ Res,
              int M, int N, int K) {
    extern __shared__ char dynsmem[];
    bf16* As = (bf16*)dynsmem;
    bf16* Bs = (bf16*)(dynsmem + ATILE * 2);

    int tid  = threadIdx.x;
    int n0   = blockIdx.x * GBN, m0 = blockIdx.y * GBM;
    int warp = tid >> 5, lane = tid & 31;
    int wm   = (warp & 3) * 32;
    int wn   = (warp >> 2) * 64;

    const bf16* Abase = A  + (size_t)m0 * K;
    const bf16* Bbase = Wt + (size_t)n0 * K;

    int mrow = lane & 7;
    int sel  = lane >> 3;
    int a_row_add = (sel & 1) * 8 + mrow;
    int a_k_add   = (sel >> 1) * 8;
    int b_row_add = (sel >> 1) * 8 + mrow;
    int b_k_add   = (sel & 1) * 8;

    uint32_t As_u = (uint32_t)__cvta_generic_to_shared(As);
    uint32_t Bs_u = (uint32_t)__cvta_generic_to_shared(Bs);

    float c[2][8][4];
    #pragma unroll
    for (int mt = 0; mt < 2; mt++)
        #pragma unroll
        for (int nt = 0; nt < 8; nt++)
            #pragma unroll
            for (int r = 0; r < 4; r++) c[mt][nt][r] = 0.f;

    auto load_tiles = [&](int buf, int k0) {
        bf16* Ad = As + buf * GBM * KSTR;
        bf16* Bd = Bs + buf * GBN * KSTR;
        #pragma unroll
        for (int i = 0; i < 4; i++) {
            int ch = tid + i * 256;
            int r = ch >> 3, cc = ch & 7;
            cp16((uint32_t)__cvta_generic_to_shared(Ad + r * KSTR + cc * 8),
                 Abase + (size_t)r * K + k0 + cc * 8);
            cp16((uint32_t)__cvta_generic_to_shared(Bd + r * KSTR + cc * 8),
                 Bbase + (size_t)r * K + k0 + cc * 8);
        }
    };

    int kTiles = K / GBK;
    load_tiles(0, 0);
    CP_COMMIT();

    for (int kt = 0; kt < kTiles; kt++) {
        int buf = kt & 1;
        if (kt + 1 < kTiles) {
            load_tiles(buf ^ 1, (kt + 1) * GBK);
            CP_COMMIT();
            CP_WAIT(1);
        } else {
            CP_WAIT(0);
        }
        __syncthreads();

        uint32_t Abuf = As_u + (uint32_t)(buf * GBM * KSTR) * 2;
        uint32_t Bbuf = Bs_u + (uint32_t)(buf * GBN * KSTR) * 2;

        #pragma unroll
        for (int ks = 0; ks < GBK; ks += 16) {
            unsigned af[2][4], bfr[8][2];
            #pragma unroll
            for (int mt = 0; mt < 2; mt++) {
                uint32_t addr = Abuf +
                    (uint32_t)((wm + mt * 16 + a_row_add) * KSTR + ks + a_k_add) * 2;
                ldsm4(af[mt][0], af[mt][1], af[mt][2], af[mt][3], addr);
            }
            #pragma unroll
            for (int np = 0; np < 4; np++) {
                uint32_t addr = Bbuf +
                    (uint32_t)((wn + np * 16 + b_row_add) * KSTR + ks + b_k_add) * 2;
                ldsm4(bfr[2*np][0], bfr[2*np][1], bfr[2*np+1][0], bfr[2*np+1][1], addr);
            }
            #pragma unroll
            for (int mt = 0; mt < 2; mt++)
                #pragma unroll
                for (int nt = 0; nt < 8; nt++)
                    mma_bf16(c[mt][nt], af[mt], bfr[nt]);
        }
        __syncthreads();
    }

    int gid  = lane >> 2, tid4 = lane & 3;

    if (EPI == 4) {
        // residual add into smem f32 tile [128][TSTR], then transposed out
        float* tileT = (float*)dynsmem;
        #pragma unroll
        for (int mt = 0; mt < 2; mt++) {
            int lr0 = wm + mt * 16 + gid;
            int lr1 = lr0 + 8;
            #pragma unroll
            for (int nt = 0; nt < 8; nt++) {
                int lc = wn + nt * 8 + 2 * tid4;
                float b0 = bias[n0 + lc], b1 = bias[n0 + lc + 1];
                const float* r0p = Res + (size_t)(m0 + lr0) * N + n0 + lc;
                const float* r1p = Res + (size_t)(m0 + lr1) * N + n0 + lc;
                float2 o0 = *(const float2*)r0p, o1 = *(const float2*)r1p;
                tileT[lr0 * TSTR + lc]     = o0.x + c[mt][nt][0] + b0;
                tileT[lr0 * TSTR + lc + 1] = o0.y + c[mt][nt][1] + b1;
                tileT[lr1 * TSTR + lc]     = o1.x + c[mt][nt][2] + b0;
                tileT[lr1 * TSTR + lc + 1] = o1.y + c[mt][nt][3] + b1;
            }
        }
        __syncthreads();
        // out[b][d][l]: b = m0/LL, l0 = m0%LL, d = n0+col. Rows of 128 floats.
        float* outp = (float*)Cv;
        int bb = m0 >> 13;              // /LL
        int l0 = m0 & (LL - 1);
        int dcol = tid >> 1;            // 0..127
        int half = (tid & 1) * 64;      // 64 tokens per half
        float* orow = outp + (size_t)bb * DIMM * LL + (size_t)(n0 + dcol) * LL + l0 + half;
        #pragma unroll
        for (int t = 0; t < 64; t += 4) {
            float4 v;
            v.x = tileT[(half + t + 0) * TSTR + dcol];
            v.y = tileT[(half + t + 1) * TSTR + dcol];
            v.z = tileT[(half + t + 2) * TSTR + dcol];
            v.w = tileT[(half + t + 3) * TSTR + dcol];
            *(float4*)(orow + t) = v;
        }
        return;
    }

    #pragma unroll
    for (int mt = 0; mt < 2; mt++) {
        int r0 = m0 + wm + mt * 16 + gid;
        int r1 = r0 + 8;
        #pragma unroll
        for (int nt = 0; nt < 8; nt++) {
            int cc = n0 + wn + nt * 8 + 2 * tid4;
            float b0 = bias[cc], b1 = bias[cc + 1];
            float v00 = c[mt][nt][0] + b0, v01 = c[mt][nt][1] + b1;
            float v10 = c[mt][nt][2] + b0, v11 = c[mt][nt][3] + b1;
            if (EPI == 0) {
                float* C = (float*)Cv;
                *(float2*)(C + (size_t)r0 * N + cc) = make_float2(v00, v01);
                *(float2*)(C + (size_t)r1 * N + cc) = make_float2(v10, v11);
            } else if (EPI == 1) {
                bf16* C = (bf16*)Cv;
                *(bf162*)(C + (size_t)r0 * N + cc) =
                    __floats2bfloat162_rn(gelu_tanh(v00), gelu_tanh(v01));
                *(bf162*)(C + (size_t)r1 * N + cc) =
                    __floats2bfloat162_rn(gelu_tanh(v10), gelu_tanh(v11));
            } else if (EPI == 2) {
                float* C = (float*)Cv;
                float* p0 = C + (size_t)r0 * N + cc;
                float* p1 = C + (size_t)r1 * N + cc;
                float2 o0 = *(float2*)p0, o1 = *(float2*)p1;
                *(float2*)p0 = make_float2(o0.x + v00, o0.y + v01);
                *(float2*)p1 = make_float2(o1.x + v10, o1.y + v11);
            } else {
                bf16* C = (bf16*)Cv;
                *(bf162*)(C + (size_t)r0 * N + cc) = __floats2bfloat162_rn(v00, v01);
                *(bf162*)(C + (size_t)r1 * N + cc) = __floats2bfloat162_rn(v10, v11);
            }
        }
    }
}

// ---------------------------------------------------------------------------
// kernel_launch
// ---------------------------------------------------------------------------
extern "C" void kernel_launch(void* const* d_in, const int* in_sizes, int n_in,
                              void* d_out, int out_size) {
    const float* x      = (const float*)d_in[0];
    const float* cosT   = (const float*)d_in[1];
    const float* sinT   = (const float*)d_in[2];
    const float* qkv_w  = (const float*)d_in[3];
    const float* qkv_b  = (const float*)d_in[4];
    const float* nq_s   = (const float*)d_in[5];
    const float* nk_s   = (const float*)d_in[6];
    const float* proj_w = (const float*)d_in[7];
    const float* proj_b = (const float*)d_in[8];
    const float* n1_s   = (const float*)d_in[9];
    const float* n2_s   = (const float*)d_in[10];
    const float* w1     = (const float*)d_in[11];
    const float* b1     = (const float*)d_in[12];
    const float* w2     = (const float*)d_in[13];
    const float* b2     = (const float*)d_in[14];
    float* out = (float*)d_out;

    float *xs, *ysum;
    bf16 *xnb, *qkvb, *ysb, *hb, *h1b, *wq, *wp, *ww1, *ww2;
    cudaGetSymbolAddress((void**)&xs,   g_xs);
    cudaGetSymbolAddress((void**)&xnb,  g_xnb);
    cudaGetSymbolAddress((void**)&qkvb, g_qkvb);
    cudaGetSymbolAddress((void**)&ysum, g_ysum);
    cudaGetSymbolAddress((void**)&ysb,  g_ysb);
    cudaGetSymbolAddress((void**)&hb,   g_hb);
    cudaGetSymbolAddress((void**)&h1b,  g_h1b);
    cudaGetSymbolAddress((void**)&wq,   g_wqkv);
    cudaGetSymbolAddress((void**)&wp,   g_wproj);
    cudaGetSymbolAddress((void**)&ww1,  g_w1);
    cudaGetSymbolAddress((void**)&ww2,  g_w2);

    cudaFuncSetAttribute(mma_gemm<1>, cudaFuncAttributeMaxDynamicSharedMemorySize, GEMM_SMEM_BYTES);
    cudaFuncSetAttribute(mma_gemm<2>, cudaFuncAttributeMaxDynamicSharedMemorySize, GEMM_SMEM_BYTES);
    cudaFuncSetAttribute(mma_gemm<3>, cudaFuncAttributeMaxDynamicSharedMemorySize, GEMM_SMEM_BYTES);
    cudaFuncSetAttribute(mma_gemm<4>, cudaFuncAttributeMaxDynamicSharedMemorySize, GEMM_SMEM_BYTES);
    cudaFuncSetAttribute(attn_mma<0, 64, 0>, cudaFuncAttributeMaxDynamicSharedMemorySize, ATTN_SMEM(64));
    cudaFuncSetAttribute(attn_mma<1, 128, 1>, cudaFuncAttributeMaxDynamicSharedMemorySize, ATTN_SMEM(128));
    cudaFuncSetAttribute(attn_mma<2, 32, 2>, cudaFuncAttributeMaxDynamicSharedMemorySize, ATTN_SMEM(32));

    dim3 tb(32, 8);

    // weight prep
    wprep_kernel<<<dim3(QKVN/32, DIMM/32), tb>>>(qkv_w, wq, DIMM, QKVN);
    wprep_kernel<<<dim3(DIMM/32, DIMM/32), tb>>>(proj_w, wp, DIMM, DIMM);
    wprep_kernel<<<dim3(FFN/32,  DIMM/32), tb>>>(w1, ww1, DIMM, FFN);
    wprep_kernel<<<dim3(DIMM/32, FFN/32),  tb>>>(w2, ww2, FFN, DIMM);

    // fused transpose + rms1
    fuse_in_kernel<<<dim3(LL/16, BB), 256>>>(x, n1_s, xs, xnb);

    // qkvb = bf16(xnb @ wq^T + qkv_b)
    mma_gemm<3><<<dim3(QKVN/GBN, NTOK/GBM), 256, GEMM_SMEM_BYTES>>>(
        xnb, wq, qkv_b, qkvb, nullptr, NTOK, QKVN, DIMM);

    // q/k rmsnorm + rope
    qkrope_kernel<<<NTOK/4, 128>>>(qkvb, nq_s, nk_s, cosT, sinT);

    // three attentions (tensor-core)
    attn_mma<0, 64,  0><<<dim3(BB * TT / 4,  NHEAD), 128, ATTN_SMEM(64)>>>(qkvb, ysum, ysb);
    attn_mma<1, 128, 1><<<dim3(BB * FRR / 4, NHEAD), 128, ATTN_SMEM(128)>>>(qkvb, ysum, ysb);
    attn_mma<2, 32,  2><<<dim3(BB * 256 / 4, NHEAD), 128, ATTN_SMEM(32)>>>(qkvb, ysum, ysb);

    // xs += ysb @ wp^T + proj_b
    mma_gemm<2><<<dim3(DIMM/GBN, NTOK/GBM), 256, GEMM_SMEM_BYTES>>>(
        ysb, wp, proj_b, xs, nullptr, NTOK, DIMM, DIMM);

    // hb = bf16(rms(xs, n2))
    rms_kernel<<<NTOK, 128>>>(xs, n2_s, hb);

    // h1b = bf16(gelu(hb @ ww1^T + b1))
    mma_gemm<1><<<dim3(FFN/GBN, NTOK/GBM), 256, GEMM_SMEM_BYTES>>>(
        hb, ww1, b1, h1b, nullptr, NTOK, FFN, DIMM);

    // out = transpose(xs + h1b @ ww2^T + b2)   (fused epilogue, no xs write)
    mma_gemm<4><<<dim3(DIMM/GBN, NTOK/GBM), 256, GEMM_SMEM_BYTES>>>(
        h1b, ww2, b2, out, xs, NTOK, DIMM, FFN);
}

// round 16
// speedup vs baseline: 1.9630x; 1.1322x over previous
#include <cuda_runtime.h>
#include <cuda_bf16.h>
#include <math.h>
#include <stdint.h>

#define BB    4
#define TT    128
#define FRR   64
#define LL    8192
#define DIMM  384
#define NHEAD 12
#define HDIM  32
#define NTOK  (BB*LL)
#define QKVN  (3*DIMM)
#define FFN   (4*DIMM)

typedef __nv_bfloat16  bf16;
typedef __nv_bfloat162 bf162;

// ---------------------------------------------------------------------------
// Scratch
// ---------------------------------------------------------------------------
__device__ float g_xs  [(size_t)NTOK * DIMM];
__device__ bf16  g_xnb [(size_t)NTOK * DIMM];
__device__ bf16  g_qkvb[(size_t)NTOK * QKVN];
__device__ bf16  g_y1b [(size_t)NTOK * DIMM];
__device__ bf16  g_y2b [(size_t)NTOK * DIMM];
__device__ bf16  g_y3b [(size_t)NTOK * DIMM];
__device__ bf16  g_ysb [(size_t)NTOK * DIMM];
__device__ bf16  g_hb  [(size_t)NTOK * DIMM];
__device__ bf16  g_h1b [(size_t)NTOK * FFN];
__device__ bf16  g_wqkv [QKVN * DIMM];
__device__ bf16  g_wproj[DIMM * DIMM];
__device__ bf16  g_w1   [FFN * DIMM];
__device__ bf16  g_w2   [DIMM * FFN];

// ---------------------------------------------------------------------------
// common PTX helpers
// ---------------------------------------------------------------------------
__device__ __forceinline__ void cp16(uint32_t smem, const void* gmem) {
    asm volatile("cp.async.cg.shared.global [%0], [%1], 16;\n" :: "r"(smem), "l"(gmem));
}
#define CP_COMMIT() asm volatile("cp.async.commit_group;\n" ::: "memory")
#define CP_WAIT(n)  asm volatile("cp.async.wait_group %0;\n" :: "n"(n) : "memory")

__device__ __forceinline__ void ldsm4(unsigned& r0, unsigned& r1,
                                      unsigned& r2, unsigned& r3, unsigned addr) {
    asm volatile("ldmatrix.sync.aligned.m8n8.x4.shared.b16 {%0,%1,%2,%3}, [%4];\n"
                 : "=r"(r0), "=r"(r1), "=r"(r2), "=r"(r3) : "r"(addr));
}

__device__ __forceinline__ void mma_bf16(float* c, const unsigned* a, const unsigned* b) {
    asm volatile(
        "mma.sync.aligned.m16n8k16.row.col.f32.bf16.bf16.f32 "
        "{%0,%1,%2,%3}, {%4,%5,%6,%7}, {%8,%9}, {%0,%1,%2,%3};\n"
        : "+f"(c[0]), "+f"(c[1]), "+f"(c[2]), "+f"(c[3])
        : "r"(a[0]), "r"(a[1]), "r"(a[2]), "r"(a[3]), "r"(b[0]), "r"(b[1]));
}

__device__ __forceinline__ unsigned packbf(float lo, float hi) {
    bf162 v = __floats2bfloat162_rn(lo, hi);
    unsigned u;
    memcpy(&u, &v, 4);
    return u;
}

__device__ __forceinline__ float2 unpackbf(unsigned u) {
    bf162 v;
    memcpy(&v, &u, 4);
    return __bfloat1622float2(v);
}

__device__ __forceinline__ float gelu_tanh(float x) {
    float c = 0.7978845608028654f;
    float t = tanhf(c * (x + 0.044715f * x * x * x));
    return 0.5f * x * (1.0f + t);
}

// ---------------------------------------------------------------------------
// Weight prep: w [K][N] f32 -> wt [N][K] bf16
// ---------------------------------------------------------------------------
__global__ void wprep_kernel(const float* __restrict__ w,
                             bf16* __restrict__ wt, int K, int N) {
    __shared__ float tile[32][33];
    int n0 = blockIdx.x * 32, k0 = blockIdx.y * 32;
    int tx = threadIdx.x, ty = threadIdx.y;
    #pragma unroll
    for (int i = 0; i < 32; i += 8)
        tile[ty + i][tx] = w[(size_t)(k0 + ty + i) * N + n0 + tx];
    __syncthreads();
    #pragma unroll
    for (int i = 0; i < 32; i += 8)
        wt[(size_t)(n0 + ty + i) * K + k0 + tx] =
            __float2bfloat16_rn(tile[tx][ty + i]);
}

// ---------------------------------------------------------------------------
// Fused input transpose + rms1
// ---------------------------------------------------------------------------
__global__ __launch_bounds__(256)
void fuse_in_kernel(const float* __restrict__ x,
                    const float* __restrict__ n1,
                    float* __restrict__ xs, bf16* __restrict__ xnb) {
    __shared__ float tile[DIMM][17];
    __shared__ float rinv[16];
    int tid = threadIdx.x;
    int l0 = blockIdx.x * 16;
    int b  = blockIdx.y;
    const float* xb = x + (size_t)b * DIMM * LL + l0;

    #pragma unroll
    for (int it = 0; it < 24; it++) {
        int idx = tid + it * 256;
        int d = idx >> 4, c = idx & 15;
        tile[d][c] = xb[(size_t)d * LL + c];
    }
    __syncthreads();

    int tok = tid >> 4, j = tid & 15;
    float s = 0.f;
    #pragma unroll
    for (int k = 0; k < 24; k++) {
        float v = tile[j + 16 * k][tok];
        s += v * v;
    }
    #pragma unroll
    for (int m = 8; m >= 1; m >>= 1)
        s += __shfl_xor_sync(0xffffffffu, s, m);
    if (j == 0) rinv[tok] = rsqrtf(s * (1.0f / DIMM) + 1e-6f);
    __syncthreads();

    size_t gbase = ((size_t)b * LL + l0) * DIMM;
    #pragma unroll
    for (int it = 0; it < 24; it++) {
        int idx = tid + it * 256;
        int t2 = idx / DIMM, d = idx - t2 * DIMM;
        float raw = tile[d][t2];
        xs[gbase + (size_t)t2 * DIMM + d] = raw;
        xnb[gbase + (size_t)t2 * DIMM + d] =
            __float2bfloat16_rn(raw * rinv[t2] * n1[d]);
    }
}

// ---------------------------------------------------------------------------
// rms2
// ---------------------------------------------------------------------------
__global__ void rms_kernel(const float* __restrict__ in,
                           const float* __restrict__ scale,
                           bf16* __restrict__ out) {
    int tok = blockIdx.x;
    int tid = threadIdx.x;
    const float* row = in + (size_t)tok * DIMM;
    float v0 = row[tid], v1 = row[tid + 128], v2 = row[tid + 256];
    float s = v0*v0 + v1*v1 + v2*v2;
    #pragma unroll
    for (int off = 16; off > 0; off >>= 1)
        s += __shfl_down_sync(0xffffffffu, s, off);
    __shared__ float red[4];
    if ((tid & 31) == 0) red[tid >> 5] = s;
    __syncthreads();
    if (tid == 0) {
        float t = red[0] + red[1] + red[2] + red[3];
        red[0] = rsqrtf(t * (1.0f / DIMM) + 1e-6f);
    }
    __syncthreads();
    float rinv = red[0];
    bf16* orow = out + (size_t)tok * DIMM;
    orow[tid]       = __float2bfloat16_rn(v0 * rinv * scale[tid]);
    orow[tid + 128] = __float2bfloat16_rn(v1 * rinv * scale[tid + 128]);
    orow[tid + 256] = __float2bfloat16_rn(v2 * rinv * scale[tid + 256]);
}

// ---------------------------------------------------------------------------
// QK rms-norm + RoPE on bf16 qkv, warp-per-token. fp32 math inside.
// ---------------------------------------------------------------------------
__global__ __launch_bounds__(128)
void qkrope_kernel(bf16* __restrict__ qkv,
                   const float* __restrict__ nq,
                   const float* __restrict__ nk,
                   const float* __restrict__ cosT,
                   const float* __restrict__ sinT) {
    int tid = threadIdx.x;
    int lane = tid & 31;
    int tok = blockIdx.x * 4 + (tid >> 5);
    size_t base = (size_t)tok * QKVN;
    bf16* qp = qkv + base;
    bf16* kp = qkv + base + DIMM;

    float q[12], k[12];
    float ssq = 0.f, ssk = 0.f;
    #pragma unroll
    for (int i = 0; i < 3; i++) {
        int e0 = i * 128 + lane * 4;
        uint2 qw = *(const uint2*)(qp + e0);
        uint2 kw = *(const uint2*)(kp + e0);
        float2 qa = unpackbf(qw.x), qb = unpackbf(qw.y);
        float2 ka = unpackbf(kw.x), kb = unpackbf(kw.y);
        q[i*4+0] = qa.x; q[i*4+1] = qa.y; q[i*4+2] = qb.x; q[i*4+3] = qb.y;
        k[i*4+0] = ka.x; k[i*4+1] = ka.y; k[i*4+2] = kb.x; k[i*4+3] = kb.y;
        ssq += qa.x*qa.x + qa.y*qa.y + qb.x*qb.x + qb.y*qb.y;
        ssk += ka.x*ka.x + ka.y*ka.y + kb.x*kb.x + kb.y*kb.y;
    }
    #pragma unroll
    for (int m = 16; m >= 1; m >>= 1) {
        ssq += __shfl_xor_sync(0xffffffffu, ssq, m);
        ssk += __shfl_xor_sync(0xffffffffu, ssk, m);
    }
    float rq = rsqrtf(ssq * (1.0f / DIMM) + 1e-6f);
    float rk = rsqrtf(ssk * (1.0f / DIMM) + 1e-6f);

    int l = tok & (LL - 1);
    int j2 = 2 * (lane & 7);
    float c0 = cosT[l * 16 + j2],     s0 = sinT[l * 16 + j2];
    float c1 = cosT[l * 16 + j2 + 1], s1 = sinT[l * 16 + j2 + 1];

    #pragma unroll
    for (int i = 0; i < 3; i++) {
        int e0 = i * 128 + lane * 4;
        float4 nqv = *(const float4*)(nq + e0);
        float4 nkv = *(const float4*)(nk + e0);
        float a0 = q[i*4+0] * rq * nqv.x, a1 = q[i*4+1] * rq * nqv.y;
        float a2 = q[i*4+2] * rq * nqv.z, a3 = q[i*4+3] * rq * nqv.w;
        uint2 qo;
        qo.x = packbf(a0 * c0 - a1 * s0, a0 * s0 + a1 * c0);
        qo.y = packbf(a2 * c1 - a3 * s1, a2 * s1 + a3 * c1);
        *(uint2*)(qp + e0) = qo;
        float b0 = k[i*4+0] * rk * nkv.x, b1 = k[i*4+1] * rk * nkv.y;
        float b2 = k[i*4+2] * rk * nkv.z, b3 = k[i*4+3] * rk * nkv.w;
        uint2 ko;
        ko.x = packbf(b0 * c0 - b1 * s0, b0 * s0 + b1 * c0);
        ko.y = packbf(b2 * c1 - b3 * s1, b2 * s1 + b3 * c1);
        *(uint2*)(kp + e0) = ko;
    }
}

// ---------------------------------------------------------------------------
// ysb = bf16(f32(y1) + f32(y2) + f32(y3)); vectorized 8 bf16 per thread.
// ---------------------------------------------------------------------------
__global__ __launch_bounds__(256)
void sum3_kernel(const bf16* __restrict__ y1, const bf16* __restrict__ y2,
                 const bf16* __restrict__ y3, bf16* __restrict__ o) {
    size_t i = ((size_t)blockIdx.x * 256 + threadIdx.x) * 8;
    uint4 a = *(const uint4*)(y1 + i);
    uint4 b = *(const uint4*)(y2 + i);
    uint4 c = *(const uint4*)(y3 + i);
    uint4 r;
    {
        float2 fa = unpackbf(a.x), fb = unpackbf(b.x), fc = unpackbf(c.x);
        r.x = packbf(fa.x + fb.x + fc.x, fa.y + fb.y + fc.y);
        fa = unpackbf(a.y); fb = unpackbf(b.y); fc = unpackbf(c.y);
        r.y = packbf(fa.x + fb.x + fc.x, fa.y + fb.y + fc.y);
        fa = unpackbf(a.z); fb = unpackbf(b.z); fc = unpackbf(c.z);
        r.z = packbf(fa.x + fb.x + fc.x, fa.y + fb.y + fc.y);
        fa = unpackbf(a.w); fb = unpackbf(b.w); fc = unpackbf(c.w);
        r.w = packbf(fa.x + fb.x + fc.x, fa.y + fb.y + fc.y);
    }
    *(uint4*)(o + i) = r;
}

// ---------------------------------------------------------------------------
// Tensor-core attention: warp-per-(group,head), bf16 mma, fp32 softmax.
// Each variant writes its own bf16 y buffer (pure stores, no RMW).
// ---------------------------------------------------------------------------
template <int VAR>
__device__ __forceinline__ int tok_of(int g, int s) {
    if (VAR == 0) { int b = g >> 7, t = g & 127; return b * LL + t * FRR + s; }
    if (VAR == 1) { int b = g >> 6, fr = g & 63; return b * LL + s * FRR + fr; }
    int b = g >> 8, r = g & 255;
    int t1 = r >> 3, f1 = r & 7;
    int t2 = s >> 3, f2 = s & 7;
    return b * LL + (t1 * 4 + t2) * FRR + f1 * 8 + f2;
}

template <int VAR, int S>
__global__ __launch_bounds__(128)
void attn_mma(const bf16* __restrict__ qkv, bf16* __restrict__ yout) {
    extern __shared__ char asmem[];
    constexpr int QSTR = 40;
    constexpr int VSTR = S + 8;
    constexpr int QSZ  = S * QSTR;
    constexpr int VTSZ = 32 * VSTR;
    constexpr int JOB  = 2 * QSZ + VTSZ;

    int tid = threadIdx.x, wid = tid >> 5, lane = tid & 31;
    int g = blockIdx.x * 4 + wid;
    int h = blockIdx.y;

    bf16* Qs = (bf16*)asmem + (size_t)wid * JOB;
    bf16* Ks = Qs + QSZ;
    bf16* Vt = Ks + QSZ;

    for (int j = 0; j < S; j++) {
        size_t base = (size_t)tok_of<VAR>(g, j) * QKVN + h * HDIM + lane;
        bf16 qv = qkv[base];
        bf16 kv = qkv[base + 384];
        bf16 vv = qkv[base + 768];
        Qs[j * QSTR + lane] = qv;
        Ks[j * QSTR + lane] = kv;
        Vt[lane * VSTR + j] = vv;
    }
    __syncwarp();

    uint32_t Qu = (uint32_t)__cvta_generic_to_shared(Qs);
    uint32_t Ku = (uint32_t)__cvta_generic_to_shared(Ks);
    uint32_t Vu = (uint32_t)__cvta_generic_to_shared(Vt);

    int mrow = lane & 7, sel = lane >> 3;
    int a_row = (sel & 1) * 8 + mrow, a_k = (sel >> 1) * 8;
    int b_row = (sel >> 1) * 8 + mrow, b_k = (sel & 1) * 8;
    int gid = lane >> 2, tid4 = lane & 3;
    const float rscale = 0.17677669529663687f;

    for (int mt = 0; mt < S / 16; mt++) {
        unsigned aq[2][4];
        #pragma unroll
        for (int ks = 0; ks < 2; ks++) {
            uint32_t addr = Qu +
                (uint32_t)((mt * 16 + a_row) * QSTR + ks * 16 + a_k) * 2;
            ldsm4(aq[ks][0], aq[ks][1], aq[ks][2], aq[ks][3], addr);
        }

        float cy[4][4];
        #pragma unroll
        for (int nt = 0; nt < 4; nt++)
            #pragma unroll
            for (int r = 0; r < 4; r++) cy[nt][r] = 0.f;
        float ls0 = 0.f, ls1 = 0.f;

        for (int jt = 0; jt < S / 16; jt++) {
            unsigned bk[2][2][2];
            #pragma unroll
            for (int ks = 0; ks < 2; ks++) {
                uint32_t addr = Ku +
                    (uint32_t)((jt * 16 + b_row) * QSTR + ks * 16 + b_k) * 2;
                ldsm4(bk[ks][0][0], bk[ks][0][1], bk[ks][1][0], bk[ks][1][1], addr);
            }
            float sc[2][4];
            #pragma unroll
            for (int nt = 0; nt < 2; nt++)
                #pragma unroll
                for (int r = 0; r < 4; r++) sc[nt][r] = 0.f;
            #pragma unroll
            for (int ks = 0; ks < 2; ks++)
                #pragma unroll
                for (int nt = 0; nt < 2; nt++)
                    mma_bf16(sc[nt], aq[ks], bk[ks][nt]);

            float p00 = __expf(sc[0][0] * rscale), p01 = __expf(sc[0][1] * rscale);
            float p02 = __expf(sc[0][2] * rscale), p03 = __expf(sc[0][3] * rscale);
            float p10 = __expf(sc[1][0] * rscale), p11 = __expf(sc[1][1] * rscale);
            float p12 = __expf(sc[1][2] * rscale), p13 = __expf(sc[1][3] * rscale);
            ls0 += p00 + p01 + p10 + p11;
            ls1 += p02 + p03 + p12 + p13;
            unsigned pa[4];
            pa[0] = packbf(p00, p01);
            pa[1] = packbf(p02, p03);
            pa[2] = packbf(p10, p11);
            pa[3] = packbf(p12, p13);

            unsigned bv[4][2];
            #pragma unroll
            for (int np = 0; np < 2; np++) {
                uint32_t addr = Vu +
                    (uint32_t)((np * 16 + b_row) * VSTR + jt * 16 + b_k) * 2;
                ldsm4(bv[2*np][0], bv[2*np][1], bv[2*np+1][0], bv[2*np+1][1], addr);
            }
            #pragma unroll
            for (int nt = 0; nt < 4; nt++)
                mma_bf16(cy[nt], pa, bv[nt]);
        }

        ls0 += __shfl_xor_sync(0xffffffffu, ls0, 1);
        ls0 += __shfl_xor_sync(0xffffffffu, ls0, 2);
        ls1 += __shfl_xor_sync(0xffffffffu, ls1, 1);
        ls1 += __shfl_xor_sync(0xffffffffu, ls1, 2);
        float inv0 = 1.f / ls0, inv1 = 1.f / ls1;

        int r0 = mt * 16 + gid, r1 = r0 + 8;
        size_t o0 = (size_t)tok_of<VAR>(g, r0) * DIMM + h * HDIM;
        size_t o1 = (size_t)tok_of<VAR>(g, r1) * DIMM + h * HDIM;
        #pragma unroll
        for (int nt = 0; nt < 4; nt++) {
            int cc = nt * 8 + 2 * tid4;
            *(bf162*)(yout + o0 + cc) =
                __floats2bfloat162_rn(cy[nt][0] * inv0, cy[nt][1] * inv0);
            *(bf162*)(yout + o1 + cc) =
                __floats2bfloat162_rn(cy[nt][2] * inv1, cy[nt][3] * inv1);
        }
    }
}

#define ATTN_SMEM(S) (4 * (2 * (S) * 40 + 32 * ((S) + 8)) * 2)

// ---------------------------------------------------------------------------
// bf16 mma.sync GEMM (2-stage cp.async, ldmatrix, GBK=64)
// EPI 0: f32 store; 1: bf16 gelu store; 2: f32 +=; 3: bf16 store;
// EPI 4: read Res (f32 residual), add, write TRANSPOSED to out (B,DIM,L).
// ---------------------------------------------------------------------------
#define GBM 128
#define GBN 128
#define GBK 64
#define KSTR 72
#define ATILE (2 * GBM * KSTR)
#define GEMM_SMEM_BYTES (2 * ATILE * 2)
#define TSTR 129

template <int EPI>
__global__ __launch_bounds__(256)
void mma_gemm(const bf16* __restrict__ A, const bf16* __restrict__ Wt,
              const float* __restrict__ bias, void* __restrict__ Cv,
              const float* __restrict__ Res,
              int M, int N, int K) {
    extern __shared__ char dynsmem[];
    bf16* As = (bf16*)dynsmem;
    bf16* Bs = (bf16*)(dynsmem + ATILE * 2);

    int tid  = threadIdx.x;
    int n0   = blockIdx.x * GBN, m0 = blockIdx.y * GBM;
    int warp = tid >> 5, lane = tid & 31;
    int wm   = (warp & 3) * 32;
    int wn   = (warp >> 2) * 64;

    const bf16* Abase = A  + (size_t)m0 * K;
    const bf16* Bbase = Wt + (size_t)n0 * K;

    int mrow = lane & 7;
    int sel  = lane >> 3;
    int a_row_add = (sel & 1) * 8 + mrow;
    int a_k_add   = (sel >> 1) * 8;
    int b_row_add = (sel >> 1) * 8 + mrow;
    int b_k_add   = (sel & 1) * 8;

    uint32_t As_u = (uint32_t)__cvta_generic_to_shared(As);
    uint32_t Bs_u = (uint32_t)__cvta_generic_to_shared(Bs);

    float c[2][8][4];
    #pragma unroll
    for (int mt = 0; mt < 2; mt++)
        #pragma unroll
        for (int nt = 0; nt < 8; nt++)
            #pragma unroll
            for (int r = 0; r < 4; r++) c[mt][nt][r] = 0.f;

    auto load_tiles = [&](int buf, int k0) {
        bf16* Ad = As + buf * GBM * KSTR;
        bf16* Bd = Bs + buf * GBN * KSTR;
        #pragma unroll
        for (int i = 0; i < 4; i++) {
            int ch = tid + i * 256;
            int r = ch >> 3, cc = ch & 7;
            cp16((uint32_t)__cvta_generic_to_shared(Ad + r * KSTR + cc * 8),
                 Abase + (size_t)r * K + k0 + cc * 8);
            cp16((uint32_t)__cvta_generic_to_shared(Bd + r * KSTR + cc * 8),
                 Bbase + (size_t)r * K + k0 + cc * 8);
        }
    };

    int kTiles = K / GBK;
    load_tiles(0, 0);
    CP_COMMIT();

    for (int kt = 0; kt < kTiles; kt++) {
        int buf = kt & 1;
        if (kt + 1 < kTiles) {
            load_tiles(buf ^ 1, (kt + 1) * GBK);
            CP_COMMIT();
            CP_WAIT(1);
        } else {
            CP_WAIT(0);
        }
        __syncthreads();

        uint32_t Abuf = As_u + (uint32_t)(buf * GBM * KSTR) * 2;
        uint32_t Bbuf = Bs_u + (uint32_t)(buf * GBN * KSTR) * 2;

        #pragma unroll
        for (int ks = 0; ks < GBK; ks += 16) {
            unsigned af[2][4], bfr[8][2];
            #pragma unroll
            for (int mt = 0; mt < 2; mt++) {
                uint32_t addr = Abuf +
                    (uint32_t)((wm + mt * 16 + a_row_add) * KSTR + ks + a_k_add) * 2;
                ldsm4(af[mt][0], af[mt][1], af[mt][2], af[mt][3], addr);
            }
            #pragma unroll
            for (int np = 0; np < 4; np++) {
                uint32_t addr = Bbuf +
                    (uint32_t)((wn + np * 16 + b_row_add) * KSTR + ks + b_k_add) * 2;
                ldsm4(bfr[2*np][0], bfr[2*np][1], bfr[2*np+1][0], bfr[2*np+1][1], addr);
            }
            #pragma unroll
            for (int mt = 0; mt < 2; mt++)
                #pragma unroll
                for (int nt = 0; nt < 8; nt++)
                    mma_bf16(c[mt][nt], af[mt], bfr[nt]);
        }
        __syncthreads();
    }

    int gid  = lane >> 2, tid4 = lane & 3;

    if (EPI == 4) {
        float* tileT = (float*)dynsmem;
        #pragma unroll
        for (int mt = 0; mt < 2; mt++) {
            int lr0 = wm + mt * 16 + gid;
            int lr1 = lr0 + 8;
            #pragma unroll
            for (int nt = 0; nt < 8; nt++) {
                int lc = wn + nt * 8 + 2 * tid4;
                float b0 = bias[n0 + lc], b1 = bias[n0 + lc + 1];
                const float* r0p = Res + (size_t)(m0 + lr0) * N + n0 + lc;
                const float* r1p = Res + (size_t)(m0 + lr1) * N + n0 + lc;
                float2 o0 = *(const float2*)r0p, o1 = *(const float2*)r1p;
                tileT[lr0 * TSTR + lc]     = o0.x + c[mt][nt][0] + b0;
                tileT[lr0 * TSTR + lc + 1] = o0.y + c[mt][nt][1] + b1;
                tileT[lr1 * TSTR + lc]     = o1.x + c[mt][nt][2] + b0;
                tileT[lr1 * TSTR + lc + 1] = o1.y + c[mt][nt][3] + b1;
            }
        }
        __syncthreads();
        float* outp = (float*)Cv;
        int bb = m0 >> 13;
        int l0 = m0 & (LL - 1);
        int dcol = tid >> 1;
        int half = (tid & 1) * 64;
        float* orow = outp + (size_t)bb * DIMM * LL + (size_t)(n0 + dcol) * LL + l0 + half;
        #pragma unroll
        for (int t = 0; t < 64; t += 4) {
            float4 v;
            v.x = tileT[(half + t + 0) * TSTR + dcol];
            v.y = tileT[(half + t + 1) * TSTR + dcol];
            v.z = tileT[(half + t + 2) * TSTR + dcol];
            v.w = tileT[(half + t + 3) * TSTR + dcol];
            *(float4*)(orow + t) = v;
        }
        return;
    }

    #pragma unroll
    for (int mt = 0; mt < 2; mt++) {
        int r0 = m0 + wm + mt * 16 + gid;
        int r1 = r0 + 8;
        #pragma unroll
        for (int nt = 0; nt < 8; nt++) {
            int cc = n0 + wn + nt * 8 + 2 * tid4;
            float b0 = bias[cc], b1 = bias[cc + 1];
            float v00 = c[mt][nt][0] + b0, v01 = c[mt][nt][1] + b1;
            float v10 = c[mt][nt][2] + b0, v11 = c[mt][nt][3] + b1;
            if (EPI == 0) {
                float* C = (float*)Cv;
                *(float2*)(C + (size_t)r0 * N + cc) = make_float2(v00, v01);
                *(float2*)(C + (size_t)r1 * N + cc) = make_float2(v10, v11);
            } else if (EPI == 1) {
                bf16* C = (bf16*)Cv;
                *(bf162*)(C + (size_t)r0 * N + cc) =
                    __floats2bfloat162_rn(gelu_tanh(v00), gelu_tanh(v01));
                *(bf162*)(C + (size_t)r1 * N + cc) =
                    __floats2bfloat162_rn(gelu_tanh(v10), gelu_tanh(v11));
            } else if (EPI == 2) {
                float* C = (float*)Cv;
                float* p0 = C + (size_t)r0 * N + cc;
                float* p1 = C + (size_t)r1 * N + cc;
                float2 o0 = *(float2*)p0, o1 = *(float2*)p1;
                *(float2*)p0 = make_float2(o0.x + v00, o0.y + v01);
                *(float2*)p1 = make_float2(o1.x + v10, o1.y + v11);
            } else {
                bf16* C = (bf16*)Cv;
                *(bf162*)(C + (size_t)r0 * N + cc) = __floats2bfloat162_rn(v00, v01);
                *(bf162*)(C + (size_t)r1 * N + cc) = __floats2bfloat162_rn(v10, v11);
            }
        }
    }
}

// ---------------------------------------------------------------------------
// kernel_launch
// ---------------------------------------------------------------------------
extern "C" void kernel_launch(void* const* d_in, const int* in_sizes, int n_in,
                              void* d_out, int out_size) {
    const float* x      = (const float*)d_in[0];
    const float* cosT   = (const float*)d_in[1];
    const float* sinT   = (const float*)d_in[2];
    const float* qkv_w  = (const float*)d_in[3];
    const float* qkv_b  = (const float*)d_in[4];
    const float* nq_s   = (const float*)d_in[5];
    const float* nk_s   = (const float*)d_in[6];
    const float* proj_w = (const float*)d_in[7];
    const float* proj_b = (const float*)d_in[8];
    const float* n1_s   = (const float*)d_in[9];
    const float* n2_s   = (const float*)d_in[10];
    const float* w1     = (const float*)d_in[11];
    const float* b1     = (const float*)d_in[12];
    const float* w2     = (const float*)d_in[13];
    const float* b2     = (const float*)d_in[14];
    float* out = (float*)d_out;

    float *xs;
    bf16 *xnb, *qkvb, *y1b, *y2b, *y3b, *ysb, *hb, *h1b, *wq, *wp, *ww1, *ww2;
    cudaGetSymbolAddress((void**)&xs,   g_xs);
    cudaGetSymbolAddress((void**)&xnb,  g_xnb);
    cudaGetSymbolAddress((void**)&qkvb, g_qkvb);
    cudaGetSymbolAddress((void**)&y1b,  g_y1b);
    cudaGetSymbolAddress((void**)&y2b,  g_y2b);
    cudaGetSymbolAddress((void**)&y3b,  g_y3b);
    cudaGetSymbolAddress((void**)&ysb,  g_ysb);
    cudaGetSymbolAddress((void**)&hb,   g_hb);
    cudaGetSymbolAddress((void**)&h1b,  g_h1b);
    cudaGetSymbolAddress((void**)&wq,   g_wqkv);
    cudaGetSymbolAddress((void**)&wp,   g_wproj);
    cudaGetSymbolAddress((void**)&ww1,  g_w1);
    cudaGetSymbolAddress((void**)&ww2,  g_w2);

    cudaFuncSetAttribute(mma_gemm<1>, cudaFuncAttributeMaxDynamicSharedMemorySize, GEMM_SMEM_BYTES);
    cudaFuncSetAttribute(mma_gemm<2>, cudaFuncAttributeMaxDynamicSharedMemorySize, GEMM_SMEM_BYTES);
    cudaFuncSetAttribute(mma_gemm<3>, cudaFuncAttributeMaxDynamicSharedMemorySize, GEMM_SMEM_BYTES);
    cudaFuncSetAttribute(mma_gemm<4>, cudaFuncAttributeMaxDynamicSharedMemorySize, GEMM_SMEM_BYTES);
    cudaFuncSetAttribute(attn_mma<0, 64>,  cudaFuncAttributeMaxDynamicSharedMemorySize, ATTN_SMEM(64));
    cudaFuncSetAttribute(attn_mma<1, 128>, cudaFuncAttributeMaxDynamicSharedMemorySize, ATTN_SMEM(128));
    cudaFuncSetAttribute(attn_mma<2, 32>,  cudaFuncAttributeMaxDynamicSharedMemorySize, ATTN_SMEM(32));

    dim3 tb(32, 8);

    // weight prep
    wprep_kernel<<<dim3(QKVN/32, DIMM/32), tb>>>(qkv_w, wq, DIMM, QKVN);
    wprep_kernel<<<dim3(DIMM/32, DIMM/32), tb>>>(proj_w, wp, DIMM, DIMM);
    wprep_kernel<<<dim3(FFN/32,  DIMM/32), tb>>>(w1, ww1, DIMM, FFN);
    wprep_kernel<<<dim3(DIMM/32, FFN/32),  tb>>>(w2, ww2, FFN, DIMM);

    // fused transpose + rms1
    fuse_in_kernel<<<dim3(LL/16, BB), 256>>>(x, n1_s, xs, xnb);

    // qkvb = bf16(xnb @ wq^T + qkv_b)
    mma_gemm<3><<<dim3(QKVN/GBN, NTOK/GBM), 256, GEMM_SMEM_BYTES>>>(
        xnb, wq, qkv_b, qkvb, nullptr, NTOK, QKVN, DIMM);

    // q/k rmsnorm + rope
    qkrope_kernel<<<NTOK/4, 128>>>(qkvb, nq_s, nk_s, cosT, sinT);

    // three attentions -> independent bf16 buffers
    attn_mma<0, 64 ><<<dim3(BB * TT / 4,  NHEAD), 128, ATTN_SMEM(64)>>>(qkvb, y1b);
    attn_mma<1, 128><<<dim3(BB * FRR / 4, NHEAD), 128, ATTN_SMEM(128)>>>(qkvb, y2b);
    attn_mma<2, 32 ><<<dim3(BB * 256 / 4, NHEAD), 128, ATTN_SMEM(32)>>>(qkvb, y3b);

    // ysb = bf16(y1 + y2 + y3)
    sum3_kernel<<<(NTOK * DIMM) / (8 * 256), 256>>>(y1b, y2b, y3b, ysb);

    // xs += ysb @ wp^T + proj_b
    mma_gemm<2><<<dim3(DIMM/GBN, NTOK/GBM), 256, GEMM_SMEM_BYTES>>>(
        ysb, wp, proj_b, xs, nullptr, NTOK, DIMM, DIMM);

    // hb = bf16(rms(xs, n2))
    rms_kernel<<<NTOK, 128>>>(xs, n2_s, hb);

    // h1b = bf16(gelu(hb @ ww1^T + b1))
    mma_gemm<1><<<dim3(FFN/GBN, NTOK/GBM), 256, GEMM_SMEM_BYTES>>>(
        hb, ww1, b1, h1b, nullptr, NTOK, FFN, DIMM);

    // out = transpose(xs + h1b @ ww2^T + b2)
    mma_gemm<4><<<dim3(DIMM/GBN, NTOK/GBM), 256, GEMM_SMEM_BYTES>>>(
        h1b, ww2, b2, out, xs, NTOK, DIMM, FFN);
}